// round 3
// baseline (speedup 1.0000x reference)
#include <cuda_runtime.h>
#include <math.h>

#define BB 32
#define NN 1025
#define DD 768
#define HH 12
#define KK 257   // context length
#define NK (NN*KK)

// ---------------- scratch (device globals; no allocs allowed) ----------------
__device__ float g_ctx [BB * KK * DD];        // [B,257,768]
__device__ float g_q   [BB * NN * DD];        // [B,1025,768]
__device__ float g_kv  [BB * KK * 2 * DD];    // [B,257,1536]  (k | v)
__device__ float g_bias[HH * NN * KK];        // [12,1025,257]
__device__ float g_o   [BB * NN * DD];        // [B,1025,768]

// ---------------- 1) tiled local pooling -> ctx ----------------
// t==0: copy register token; t>=1: softmax-pool 2x2 tile (t-1)
__global__ __launch_bounds__(256)
void pool_kernel(const float* __restrict__ x, const float* __restrict__ Wl,
                 float* __restrict__ ctx)
{
    __shared__ float xs[4][768];
    __shared__ float red[4][8];
    __shared__ float ws[4];
    int t = blockIdx.x, b = blockIdx.y;
    int tid = threadIdx.x;
    const float* xb = x + (size_t)b * NN * DD;
    float* cout = ctx + ((size_t)b * KK + t) * DD;

    if (t == 0) {
        for (int i = tid; i < 192; i += 256)
            ((float4*)cout)[i] = ((const float4*)xb)[i];
        return;
    }
    int tt = t - 1, ti = tt >> 4, tj = tt & 15;
    int rows[4];
#pragma unroll
    for (int i = 0; i < 4; i++)
        rows[i] = 1 + (ti * 2 + (i >> 1)) * 32 + tj * 2 + (i & 1);

    for (int i = tid; i < 4 * 192; i += 256) {
        int rr = i / 192, seg = i - rr * 192;
        ((float4*)&xs[rr][0])[seg] = ((const float4*)(xb + (size_t)rows[rr] * DD))[seg];
    }
    __syncthreads();

    float p0 = 0.f, p1 = 0.f, p2 = 0.f, p3 = 0.f;
    for (int dm = tid; dm < DD; dm += 256) {
        float wv = Wl[dm];
        p0 = fmaf(xs[0][dm], wv, p0);
        p1 = fmaf(xs[1][dm], wv, p1);
        p2 = fmaf(xs[2][dm], wv, p2);
        p3 = fmaf(xs[3][dm], wv, p3);
    }
#pragma unroll
    for (int off = 16; off; off >>= 1) {
        p0 += __shfl_xor_sync(0xffffffffu, p0, off);
        p1 += __shfl_xor_sync(0xffffffffu, p1, off);
        p2 += __shfl_xor_sync(0xffffffffu, p2, off);
        p3 += __shfl_xor_sync(0xffffffffu, p3, off);
    }
    if ((tid & 31) == 0) {
        int wgi = tid >> 5;
        red[0][wgi] = p0; red[1][wgi] = p1; red[2][wgi] = p2; red[3][wgi] = p3;
    }
    __syncthreads();
    if (tid == 0) {
        float s[4];
#pragma unroll
        for (int i = 0; i < 4; i++) {
            float a = 0.f;
#pragma unroll
            for (int wgi = 0; wgi < 8; wgi++) a += red[i][wgi];
            s[i] = a;
        }
        float mx = fmaxf(fmaxf(s[0], s[1]), fmaxf(s[2], s[3]));
        float e0 = __expf(s[0] - mx), e1 = __expf(s[1] - mx);
        float e2 = __expf(s[2] - mx), e3 = __expf(s[3] - mx);
        float inv = 1.f / (e0 + e1 + e2 + e3);
        ws[0] = e0 * inv; ws[1] = e1 * inv; ws[2] = e2 * inv; ws[3] = e3 * inv;
    }
    __syncthreads();
    for (int dm = tid; dm < DD; dm += 256) {
        cout[dm] = ws[0] * xs[0][dm] + ws[1] * xs[1][dm]
                 + ws[2] * xs[2][dm] + ws[3] * xs[3][dm];
    }
}

// ---------------- 2) NT SGEMM: C[m,n] = sum_k A[m,k]*B[n,k] (+bias[n]) -------
// 128x128 block tile, 16 k-tile, 8x8 per thread, 256 threads.
__global__ __launch_bounds__(256, 2)
void sgemm_nt(const float* __restrict__ A, const float* __restrict__ B,
              float* __restrict__ C, int M, int N, int K,
              const float* __restrict__ bias)
{
    __shared__ float As[16][132];
    __shared__ float Bs[16][132];
    const int bm = blockIdx.y * 128;
    const int bn = blockIdx.x * 128;
    const int tid = threadIdx.x;
    const int tx = (tid & 15) * 8;
    const int ty = (tid >> 4) * 8;
    const int lr = tid >> 2;          // 0..63
    const int lc = (tid & 3) << 2;    // 0,4,8,12

    float acc[8][8];
#pragma unroll
    for (int i = 0; i < 8; i++)
#pragma unroll
        for (int j = 0; j < 8; j++) acc[i][j] = 0.f;

    for (int k0 = 0; k0 < K; k0 += 16) {
#pragma unroll
        for (int i = 0; i < 2; i++) {
            int arow = bm + lr + i * 64;
            float4 av = make_float4(0.f, 0.f, 0.f, 0.f);
            if (arow < M) av = *(const float4*)(A + (size_t)arow * K + k0 + lc);
            As[lc + 0][lr + i * 64] = av.x;
            As[lc + 1][lr + i * 64] = av.y;
            As[lc + 2][lr + i * 64] = av.z;
            As[lc + 3][lr + i * 64] = av.w;
            int brow = bn + lr + i * 64;   // N is always a multiple of 128 here
            float4 bv = *(const float4*)(B + (size_t)brow * K + k0 + lc);
            Bs[lc + 0][lr + i * 64] = bv.x;
            Bs[lc + 1][lr + i * 64] = bv.y;
            Bs[lc + 2][lr + i * 64] = bv.z;
            Bs[lc + 3][lr + i * 64] = bv.w;
        }
        __syncthreads();
#pragma unroll
        for (int kk = 0; kk < 16; kk++) {
            float a[8], bfr[8];
#pragma unroll
            for (int i = 0; i < 8; i++) a[i] = As[kk][ty + i];
#pragma unroll
            for (int j = 0; j < 8; j++) bfr[j] = Bs[kk][tx + j];
#pragma unroll
            for (int i = 0; i < 8; i++)
#pragma unroll
                for (int j = 0; j < 8; j++)
                    acc[i][j] = fmaf(a[i], bfr[j], acc[i][j]);
        }
        __syncthreads();
    }

    float bv[8];
#pragma unroll
    for (int j = 0; j < 8; j++) bv[j] = 0.f;
    if (bias) {
#pragma unroll
        for (int j = 0; j < 8; j++) bv[j] = bias[bn + tx + j];
    }
#pragma unroll
    for (int i = 0; i < 8; i++) {
        int row = bm + ty + i;
        if (row < M) {
            float* cp = C + (size_t)row * N + bn + tx;
#pragma unroll
            for (int j = 0; j < 8; j++) cp[j] = acc[i][j] + bv[j];
        }
    }
}

// ---------------- 3) CPB relative-position bias ----------------
__global__ __launch_bounds__(128)
void cpb_kernel(const float* __restrict__ feats, const float* __restrict__ mask,
                const float* __restrict__ w1, const float* __restrict__ b1,
                const float* __restrict__ w2, const float* __restrict__ b2,
                float* __restrict__ bias)
{
    int idx = blockIdx.x * blockDim.x + threadIdx.x;
    if (idx >= NK) return;
    float f0 = feats[2 * idx], f1 = feats[2 * idx + 1];
    float m = mask[idx];
    float h[32];
#pragma unroll
    for (int c = 0; c < 32; c++) {
        float t = fmaf(f0, w1[2 * c], fmaf(f1, w1[2 * c + 1], b1[c]));
        h[c] = 0.5f * t * (1.f + erff(t * 0.7071067811865475f));  // exact GELU
    }
#pragma unroll
    for (int hh = 0; hh < HH; hh++) {
        float s = b2[hh];
#pragma unroll
        for (int c = 0; c < 32; c++) s = fmaf(w2[hh * 32 + c], h[c], s);
        bias[(size_t)hh * NK + idx] = s * m;
    }
}

// ---------------- 4) attention: smem-resident K/V per (b,h) ----------------
// grid = B*H blocks, 256 threads (8 warps); each warp handles one query/iter.
__global__ __launch_bounds__(256, 1)
void attn_kernel(const float* __restrict__ q, const float* __restrict__ kv,
                 const float* __restrict__ bias, float* __restrict__ o)
{
    extern __shared__ float4 sm4[];
    float4* Ks = sm4;                   // 257 rows x 17 float4 (padded)
    float4* Vs = sm4 + 257 * 17;        // 258 rows x 17 float4
    float*  ps = (float*)(Vs + 258 * 17); // 8 warps x 264 floats

    int b = blockIdx.x / HH, h = blockIdx.x % HH;
    int tid = threadIdx.x, w = tid >> 5, l = tid & 31;

    const float* kbase = kv + (size_t)b * KK * (2 * DD) + h * 64;
    for (int i = tid; i < KK * 16; i += 256) {
        int kk = i >> 4, seg = i & 15;
        Ks[kk * 17 + seg] = *(const float4*)(kbase + (size_t)kk * (2 * DD) + seg * 4);
        Vs[kk * 17 + seg] = *(const float4*)(kbase + (size_t)kk * (2 * DD) + DD + seg * 4);
    }
    if (tid < 17) Vs[257 * 17 + tid] = make_float4(0.f, 0.f, 0.f, 0.f); // pad row
    __syncthreads();

    float* myp = ps + w * 264;
    for (int n0 = 0; n0 < NN; n0 += 8) {
        int n = n0 + w;
        if (n >= NN) break;   // per-warp independent; no block barriers below

        const float4* qp = (const float4*)(q + ((size_t)b * NN + n) * DD + h * 64);
        float4 qr[16];
#pragma unroll
        for (int i = 0; i < 16; i++) qr[i] = qp[i];

        const float* bp = bias + ((size_t)h * NN + n) * KK;
        float lr[9];
#pragma unroll
        for (int j = 0; j < 9; j++) {
            int k = l + j * 32;
            float s = -1e30f;
            if (k < KK) {
                const float4* kp = Ks + k * 17;
                float acc = 0.f;
#pragma unroll
                for (int t = 0; t < 16; t++) {
                    float4 kv4 = kp[t];
                    acc = fmaf(qr[t].x, kv4.x, acc);
                    acc = fmaf(qr[t].y, kv4.y, acc);
                    acc = fmaf(qr[t].z, kv4.z, acc);
                    acc = fmaf(qr[t].w, kv4.w, acc);
                }
                s = acc * 0.125f + bp[k];
            }
            lr[j] = s;
        }
        float mx = lr[0];
#pragma unroll
        for (int j = 1; j < 9; j++) mx = fmaxf(mx, lr[j]);
#pragma unroll
        for (int off = 16; off; off >>= 1)
            mx = fmaxf(mx, __shfl_xor_sync(0xffffffffu, mx, off));
        float sum = 0.f;
#pragma unroll
        for (int j = 0; j < 9; j++) {
            int k = l + j * 32;
            float e = (k < KK) ? __expf(lr[j] - mx) : 0.f;
            lr[j] = e; sum += e;
        }
#pragma unroll
        for (int off = 16; off; off >>= 1)
            sum += __shfl_xor_sync(0xffffffffu, sum, off);
        float inv = 1.f / sum;
#pragma unroll
        for (int j = 0; j < 9; j++) {
            int k = l + j * 32;
            if (k < 264) myp[k] = lr[j] * inv;  // k in [257,264) stores 0
        }
        __syncwarp();

        // P @ V : lanes 0-15 even k, 16-31 odd k; chunk = head-dim float4
        int chunk = l & 15, ko = l >> 4;
        float4 a4 = make_float4(0.f, 0.f, 0.f, 0.f);
        for (int kb = 0; kb <= 256; kb += 2) {
            int k = kb + ko;            // reaches 257 -> zero pad row/p
            float p = myp[k];
            float4 v = Vs[k * 17 + chunk];
            a4.x = fmaf(p, v.x, a4.x);
            a4.y = fmaf(p, v.y, a4.y);
            a4.z = fmaf(p, v.z, a4.z);
            a4.w = fmaf(p, v.w, a4.w);
        }
        a4.x += __shfl_xor_sync(0xffffffffu, a4.x, 16);
        a4.y += __shfl_xor_sync(0xffffffffu, a4.y, 16);
        a4.z += __shfl_xor_sync(0xffffffffu, a4.z, 16);
        a4.w += __shfl_xor_sync(0xffffffffu, a4.w, 16);
        if (l < 16)
            *(float4*)(o + ((size_t)b * NN + n) * DD + h * 64 + chunk * 4) = a4;
        __syncwarp();
    }
}

// ---------------- launch ----------------
extern "C" void kernel_launch(void* const* d_in, const int* in_sizes, int n_in,
                              void* d_out, int out_size)
{
    const float* x     = (const float*)d_in[0];
    const float* Wl    = (const float*)d_in[1];
    const float* Wq    = (const float*)d_in[2];
    const float* Wkv   = (const float*)d_in[3];
    const float* Wo    = (const float*)d_in[4];
    const float* bo    = (const float*)d_in[5];
    const float* w1    = (const float*)d_in[6];
    const float* b1    = (const float*)d_in[7];
    const float* w2    = (const float*)d_in[8];
    const float* b2    = (const float*)d_in[9];
    const float* feats = (const float*)d_in[10];
    const float* mask  = (const float*)d_in[11];
    float* out = (float*)d_out;

    float *ctx, *qb, *kvb, *biasb, *ob;
    cudaGetSymbolAddress((void**)&ctx,   g_ctx);
    cudaGetSymbolAddress((void**)&qb,    g_q);
    cudaGetSymbolAddress((void**)&kvb,   g_kv);
    cudaGetSymbolAddress((void**)&biasb, g_bias);
    cudaGetSymbolAddress((void**)&ob,    g_o);

    const int ATTN_SMEM = (257 * 17 + 258 * 17) * 16 + 8 * 264 * 4; // 148528 B
    cudaFuncSetAttribute(attn_kernel, cudaFuncAttributeMaxDynamicSharedMemorySize,
                         ATTN_SMEM);

    // 1. pooled context (tile 0 = register-token copy)
    pool_kernel<<<dim3(KK, BB), 256>>>(x, Wl, ctx);
    // 2. Q = x @ Wq^T    [32800,768]
    sgemm_nt<<<dim3(6, 257), 256>>>(x, Wq, qb, BB * NN, DD, DD, nullptr);
    // 3. KV = ctx @ Wkv^T [8224,1536]
    sgemm_nt<<<dim3(12, 65), 256>>>(ctx, Wkv, kvb, BB * KK, 2 * DD, DD, nullptr);
    // 4. CPB bias [12,1025,257]
    cpb_kernel<<<(NK + 127) / 128, 128>>>(feats, mask, w1, b1, w2, b2, biasb);
    // 5. attention
    attn_kernel<<<BB * HH, 256, ATTN_SMEM>>>(qb, kvb, biasb, ob);
    // 6. out = o @ Wo^T + bo
    sgemm_nt<<<dim3(6, 257), 256>>>(ob, Wo, out, BB * NN, DD, DD, bo);
}

// round 4
// speedup vs baseline: 1.3830x; 1.3830x over previous
#include <cuda_runtime.h>
#include <math.h>

#define BB 32
#define NN 1025
#define DD 768
#define HH 12
#define KK 257   // context length
#define NK (NN*KK)

// ---------------- scratch (device globals; no allocs allowed) ----------------
__device__ float g_ctx [BB * KK * DD];        // [B,257,768]
__device__ float g_q   [BB * NN * DD];        // [B,1025,768]
__device__ float g_kv  [BB * KK * 2 * DD];    // [B,257,1536]  (k | v)
__device__ float g_bias[HH * NN * KK];        // [12,1025,257]
__device__ float g_o   [BB * NN * DD];        // [B,1025,768]

// ---------------- 1) tiled local pooling -> ctx ----------------
__global__ __launch_bounds__(256)
void pool_kernel(const float* __restrict__ x, const float* __restrict__ Wl,
                 float* __restrict__ ctx)
{
    __shared__ float xs[4][768];
    __shared__ float red[4][8];
    __shared__ float ws[4];
    int t = blockIdx.x, b = blockIdx.y;
    int tid = threadIdx.x;
    const float* xb = x + (size_t)b * NN * DD;
    float* cout = ctx + ((size_t)b * KK + t) * DD;

    if (t == 0) {
        for (int i = tid; i < 192; i += 256)
            ((float4*)cout)[i] = ((const float4*)xb)[i];
        return;
    }
    int tt = t - 1, ti = tt >> 4, tj = tt & 15;
    int rows[4];
#pragma unroll
    for (int i = 0; i < 4; i++)
        rows[i] = 1 + (ti * 2 + (i >> 1)) * 32 + tj * 2 + (i & 1);

    for (int i = tid; i < 4 * 192; i += 256) {
        int rr = i / 192, seg = i - rr * 192;
        ((float4*)&xs[rr][0])[seg] = ((const float4*)(xb + (size_t)rows[rr] * DD))[seg];
    }
    __syncthreads();

    float p0 = 0.f, p1 = 0.f, p2 = 0.f, p3 = 0.f;
    for (int dm = tid; dm < DD; dm += 256) {
        float wv = Wl[dm];
        p0 = fmaf(xs[0][dm], wv, p0);
        p1 = fmaf(xs[1][dm], wv, p1);
        p2 = fmaf(xs[2][dm], wv, p2);
        p3 = fmaf(xs[3][dm], wv, p3);
    }
#pragma unroll
    for (int off = 16; off; off >>= 1) {
        p0 += __shfl_xor_sync(0xffffffffu, p0, off);
        p1 += __shfl_xor_sync(0xffffffffu, p1, off);
        p2 += __shfl_xor_sync(0xffffffffu, p2, off);
        p3 += __shfl_xor_sync(0xffffffffu, p3, off);
    }
    if ((tid & 31) == 0) {
        int wgi = tid >> 5;
        red[0][wgi] = p0; red[1][wgi] = p1; red[2][wgi] = p2; red[3][wgi] = p3;
    }
    __syncthreads();
    if (tid == 0) {
        float s[4];
#pragma unroll
        for (int i = 0; i < 4; i++) {
            float a = 0.f;
#pragma unroll
            for (int wgi = 0; wgi < 8; wgi++) a += red[i][wgi];
            s[i] = a;
        }
        float mx = fmaxf(fmaxf(s[0], s[1]), fmaxf(s[2], s[3]));
        float e0 = __expf(s[0] - mx), e1 = __expf(s[1] - mx);
        float e2 = __expf(s[2] - mx), e3 = __expf(s[3] - mx);
        float inv = 1.f / (e0 + e1 + e2 + e3);
        ws[0] = e0 * inv; ws[1] = e1 * inv; ws[2] = e2 * inv; ws[3] = e3 * inv;
    }
    __syncthreads();
    for (int dm = tid; dm < DD; dm += 256) {
        cout[dm] = ws[0] * xs[0][dm] + ws[1] * xs[1][dm]
                 + ws[2] * xs[2][dm] + ws[3] * xs[3][dm];
    }
}

// ---------------- 2) tf32 tensor-core NT GEMM ----------------
// C[m,n] = sum_k A[m,k]*B[n,k] (+bias[n]).  128x128 block, BK=16,
// 8 warps (2x4), warp tile 64x32, mma.m16n8k8.tf32, double-buffered smem.
__device__ __forceinline__ unsigned f2tf(float f) {
    unsigned u; asm("cvt.rna.tf32.f32 %0, %1;" : "=r"(u) : "f"(f)); return u;
}

#define MMA_TF32(cc, aa, bb)                                                   \
    asm volatile("mma.sync.aligned.m16n8k8.row.col.f32.tf32.tf32.f32 "         \
                 "{%0,%1,%2,%3}, {%4,%5,%6,%7}, {%8,%9}, {%0,%1,%2,%3};"       \
                 : "+f"(cc[0]), "+f"(cc[1]), "+f"(cc[2]), "+f"(cc[3])          \
                 : "r"(aa[0]), "r"(aa[1]), "r"(aa[2]), "r"(aa[3]),             \
                   "r"(bb[0]), "r"(bb[1]));

__global__ __launch_bounds__(256, 1)
void gemm_tf32(const float* __restrict__ A, const float* __restrict__ B,
               float* __restrict__ C, int M, int N, int K,
               const float* __restrict__ bias)
{
    // [row][k] layout, stride 20 words: conflict-free fragment LDS.
    __shared__ __align__(16) unsigned As[2][128][20];
    __shared__ __align__(16) unsigned Bs[2][128][20];

    const int tid  = threadIdx.x;
    const int lane = tid & 31, w = tid >> 5;
    const int g = lane >> 2, t4 = lane & 3;
    const int wm = (w >> 2) * 64;            // 0 or 64
    const int wn = (w & 3) * 32;             // 0,32,64,96
    const int bm = blockIdx.y * 128, bn = blockIdx.x * 128;

    const int lrow = tid >> 2;               // 0..63
    const int lk   = (tid & 3) << 2;         // 0,4,8,12

    float c[4][4][4];
#pragma unroll
    for (int i = 0; i < 4; i++)
#pragma unroll
        for (int j = 0; j < 4; j++)
#pragma unroll
            for (int e = 0; e < 4; e++) c[i][j][e] = 0.f;

    float4 pa[2], pb[2];
    const float4 z4 = make_float4(0.f, 0.f, 0.f, 0.f);

    const int nkt = K / 16;

    // --- prefetch tile 0 ---
#pragma unroll
    for (int i = 0; i < 2; i++) {
        int ar = bm + lrow + i * 64;
        pa[i] = (ar < M) ? *(const float4*)(A + (size_t)ar * K + lk) : z4;
        int br = bn + lrow + i * 64;          // N is a multiple of 128
        pb[i] = *(const float4*)(B + (size_t)br * K + lk);
    }
#pragma unroll
    for (int i = 0; i < 2; i++) {
        *(uint4*)&As[0][lrow + i * 64][lk] =
            make_uint4(f2tf(pa[i].x), f2tf(pa[i].y), f2tf(pa[i].z), f2tf(pa[i].w));
        *(uint4*)&Bs[0][lrow + i * 64][lk] =
            make_uint4(f2tf(pb[i].x), f2tf(pb[i].y), f2tf(pb[i].z), f2tf(pb[i].w));
    }
    __syncthreads();

    for (int kt = 0; kt < nkt; kt++) {
        const int buf = kt & 1;
        if (kt + 1 < nkt) {
            const int k0 = (kt + 1) * 16;
#pragma unroll
            for (int i = 0; i < 2; i++) {
                int ar = bm + lrow + i * 64;
                pa[i] = (ar < M) ? *(const float4*)(A + (size_t)ar * K + k0 + lk) : z4;
                int br = bn + lrow + i * 64;
                pb[i] = *(const float4*)(B + (size_t)br * K + k0 + lk);
            }
        }
#pragma unroll
        for (int ks = 0; ks < 2; ks++) {
            const int kk = ks * 8;
            unsigned af[4][4], bf[4][2];
#pragma unroll
            for (int i = 0; i < 4; i++) {
                int r = wm + i * 16 + g;
                af[i][0] = As[buf][r    ][kk + t4];
                af[i][1] = As[buf][r + 8][kk + t4];
                af[i][2] = As[buf][r    ][kk + t4 + 4];
                af[i][3] = As[buf][r + 8][kk + t4 + 4];
            }
#pragma unroll
            for (int j = 0; j < 4; j++) {
                int r = wn + j * 8 + g;
                bf[j][0] = Bs[buf][r][kk + t4];
                bf[j][1] = Bs[buf][r][kk + t4 + 4];
            }
#pragma unroll
            for (int i = 0; i < 4; i++)
#pragma unroll
                for (int j = 0; j < 4; j++)
                    MMA_TF32(c[i][j], af[i], bf[j]);
        }
        if (kt + 1 < nkt) {
            const int nb = buf ^ 1;
#pragma unroll
            for (int i = 0; i < 2; i++) {
                *(uint4*)&As[nb][lrow + i * 64][lk] =
                    make_uint4(f2tf(pa[i].x), f2tf(pa[i].y), f2tf(pa[i].z), f2tf(pa[i].w));
                *(uint4*)&Bs[nb][lrow + i * 64][lk] =
                    make_uint4(f2tf(pb[i].x), f2tf(pb[i].y), f2tf(pb[i].z), f2tf(pb[i].w));
            }
            __syncthreads();
        }
    }

    // --- epilogue ---
#pragma unroll
    for (int j = 0; j < 4; j++) {
        const int col = bn + wn + j * 8 + t4 * 2;
        float b0 = bias ? bias[col] : 0.f;
        float b1 = bias ? bias[col + 1] : 0.f;
#pragma unroll
        for (int i = 0; i < 4; i++) {
            int r0 = bm + wm + i * 16 + g;
            if (r0 < M)
                *(float2*)(C + (size_t)r0 * N + col) =
                    make_float2(c[i][j][0] + b0, c[i][j][1] + b1);
            int r1 = r0 + 8;
            if (r1 < M)
                *(float2*)(C + (size_t)r1 * N + col) =
                    make_float2(c[i][j][2] + b0, c[i][j][3] + b1);
        }
    }
}

// ---------------- 3) CPB relative-position bias ----------------
__global__ __launch_bounds__(128)
void cpb_kernel(const float* __restrict__ feats, const float* __restrict__ mask,
                const float* __restrict__ w1, const float* __restrict__ b1,
                const float* __restrict__ w2, const float* __restrict__ b2,
                float* __restrict__ bias)
{
    int idx = blockIdx.x * blockDim.x + threadIdx.x;
    if (idx >= NK) return;
    float f0 = feats[2 * idx], f1 = feats[2 * idx + 1];
    float m = mask[idx];
    float h[32];
#pragma unroll
    for (int c = 0; c < 32; c++) {
        float t = fmaf(f0, w1[2 * c], fmaf(f1, w1[2 * c + 1], b1[c]));
        h[c] = 0.5f * t * (1.f + erff(t * 0.7071067811865475f));  // exact GELU
    }
#pragma unroll
    for (int hh = 0; hh < HH; hh++) {
        float s = b2[hh];
#pragma unroll
        for (int c = 0; c < 32; c++) s = fmaf(w2[hh * 32 + c], h[c], s);
        bias[(size_t)hh * NK + idx] = s * m;
    }
}

// ---------------- 4) attention: smem-resident K/V per (b,h) ----------------
__global__ __launch_bounds__(256, 1)
void attn_kernel(const float* __restrict__ q, const float* __restrict__ kv,
                 const float* __restrict__ bias, float* __restrict__ o)
{
    extern __shared__ float4 sm4[];
    float4* Ks = sm4;                   // 257 rows x 17 float4 (padded)
    float4* Vs = sm4 + 257 * 17;        // 258 rows x 17 float4
    float*  ps = (float*)(Vs + 258 * 17); // 8 warps x 264 floats

    int b = blockIdx.x / HH, h = blockIdx.x % HH;
    int tid = threadIdx.x, w = tid >> 5, l = tid & 31;

    const float* kbase = kv + (size_t)b * KK * (2 * DD) + h * 64;
    for (int i = tid; i < KK * 16; i += 256) {
        int kk = i >> 4, seg = i & 15;
        Ks[kk * 17 + seg] = *(const float4*)(kbase + (size_t)kk * (2 * DD) + seg * 4);
        Vs[kk * 17 + seg] = *(const float4*)(kbase + (size_t)kk * (2 * DD) + DD + seg * 4);
    }
    if (tid < 17) Vs[257 * 17 + tid] = make_float4(0.f, 0.f, 0.f, 0.f); // pad row
    __syncthreads();

    float* myp = ps + w * 264;
    for (int n0 = 0; n0 < NN; n0 += 8) {
        int n = n0 + w;
        if (n >= NN) break;

        const float4* qp = (const float4*)(q + ((size_t)b * NN + n) * DD + h * 64);
        float4 qr[16];
#pragma unroll
        for (int i = 0; i < 16; i++) qr[i] = qp[i];

        const float* bp = bias + ((size_t)h * NN + n) * KK;
        float lr[9];
#pragma unroll
        for (int j = 0; j < 9; j++) {
            int k = l + j * 32;
            float s = -1e30f;
            if (k < KK) {
                const float4* kp = Ks + k * 17;
                float acc = 0.f;
#pragma unroll
                for (int t = 0; t < 16; t++) {
                    float4 kv4 = kp[t];
                    acc = fmaf(qr[t].x, kv4.x, acc);
                    acc = fmaf(qr[t].y, kv4.y, acc);
                    acc = fmaf(qr[t].z, kv4.z, acc);
                    acc = fmaf(qr[t].w, kv4.w, acc);
                }
                s = acc * 0.125f + bp[k];
            }
            lr[j] = s;
        }
        float mx = lr[0];
#pragma unroll
        for (int j = 1; j < 9; j++) mx = fmaxf(mx, lr[j]);
#pragma unroll
        for (int off = 16; off; off >>= 1)
            mx = fmaxf(mx, __shfl_xor_sync(0xffffffffu, mx, off));
        float sum = 0.f;
#pragma unroll
        for (int j = 0; j < 9; j++) {
            int k = l + j * 32;
            float e = (k < KK) ? __expf(lr[j] - mx) : 0.f;
            lr[j] = e; sum += e;
        }
#pragma unroll
        for (int off = 16; off; off >>= 1)
            sum += __shfl_xor_sync(0xffffffffu, sum, off);
        float inv = 1.f / sum;
#pragma unroll
        for (int j = 0; j < 9; j++) {
            int k = l + j * 32;
            if (k < 264) myp[k] = lr[j] * inv;
        }
        __syncwarp();

        int chunk = l & 15, ko = l >> 4;
        float4 a4 = make_float4(0.f, 0.f, 0.f, 0.f);
        for (int kb = 0; kb <= 256; kb += 2) {
            int k = kb + ko;
            float p = myp[k];
            float4 v = Vs[k * 17 + chunk];
            a4.x = fmaf(p, v.x, a4.x);
            a4.y = fmaf(p, v.y, a4.y);
            a4.z = fmaf(p, v.z, a4.z);
            a4.w = fmaf(p, v.w, a4.w);
        }
        a4.x += __shfl_xor_sync(0xffffffffu, a4.x, 16);
        a4.y += __shfl_xor_sync(0xffffffffu, a4.y, 16);
        a4.z += __shfl_xor_sync(0xffffffffu, a4.z, 16);
        a4.w += __shfl_xor_sync(0xffffffffu, a4.w, 16);
        if (l < 16)
            *(float4*)(o + ((size_t)b * NN + n) * DD + h * 64 + chunk * 4) = a4;
        __syncwarp();
    }
}

// ---------------- launch ----------------
extern "C" void kernel_launch(void* const* d_in, const int* in_sizes, int n_in,
                              void* d_out, int out_size)
{
    const float* x     = (const float*)d_in[0];
    const float* Wl    = (const float*)d_in[1];
    const float* Wq    = (const float*)d_in[2];
    const float* Wkv   = (const float*)d_in[3];
    const float* Wo    = (const float*)d_in[4];
    const float* bo    = (const float*)d_in[5];
    const float* w1    = (const float*)d_in[6];
    const float* b1    = (const float*)d_in[7];
    const float* w2    = (const float*)d_in[8];
    const float* b2    = (const float*)d_in[9];
    const float* feats = (const float*)d_in[10];
    const float* mask  = (const float*)d_in[11];
    float* out = (float*)d_out;

    float *ctx, *qb, *kvb, *biasb, *ob;
    cudaGetSymbolAddress((void**)&ctx,   g_ctx);
    cudaGetSymbolAddress((void**)&qb,    g_q);
    cudaGetSymbolAddress((void**)&kvb,   g_kv);
    cudaGetSymbolAddress((void**)&biasb, g_bias);
    cudaGetSymbolAddress((void**)&ob,    g_o);

    const int ATTN_SMEM = (257 * 17 + 258 * 17) * 16 + 8 * 264 * 4; // 148528 B
    cudaFuncSetAttribute(attn_kernel, cudaFuncAttributeMaxDynamicSharedMemorySize,
                         ATTN_SMEM);

    // 1. pooled context (tile 0 = register-token copy)
    pool_kernel<<<dim3(KK, BB), 256>>>(x, Wl, ctx);
    // 2. Q = x @ Wq^T    [32800,768]
    gemm_tf32<<<dim3(6, 257), 256>>>(x, Wq, qb, BB * NN, DD, DD, nullptr);
    // 3. KV = ctx @ Wkv^T [8224,1536]
    gemm_tf32<<<dim3(12, 65), 256>>>(ctx, Wkv, kvb, BB * KK, 2 * DD, DD, nullptr);
    // 4. CPB bias [12,1025,257]
    cpb_kernel<<<(NK + 127) / 128, 128>>>(feats, mask, w1, b1, w2, b2, biasb);
    // 5. attention
    attn_kernel<<<BB * HH, 256, ATTN_SMEM>>>(qb, kvb, biasb, ob);
    // 6. out = o @ Wo^T + bo
    gemm_tf32<<<dim3(6, 257), 256>>>(ob, Wo, out, BB * NN, DD, DD, bo);
}

// round 7
// speedup vs baseline: 2.5780x; 1.8641x over previous
#include <cuda_runtime.h>
#include <math.h>

#define BB 32
#define NN 1025
#define DD 768
#define HH 12
#define KK 257   // context length
#define NK (NN*KK)

// ---------------- scratch (device globals; no allocs allowed) ----------------
__device__ float g_ctx [BB * KK * DD];        // [B,257,768]
__device__ float g_q   [BB * NN * DD];        // [B,1025,768]
__device__ float g_kv  [BB * KK * 2 * DD];    // [B,257,1536]  (k | v)
__device__ float g_bias[HH * NN * KK];        // [12,1025,257]
__device__ float g_o   [BB * NN * DD];        // [B,1025,768]

// ---------------- helpers ----------------
__device__ __forceinline__ unsigned f2tf(float f) {
    unsigned u; asm("cvt.rna.tf32.f32 %0, %1;" : "=r"(u) : "f"(f)); return u;
}

#define MMA_TF32(cc, aa, bb)                                                   \
    asm volatile("mma.sync.aligned.m16n8k8.row.col.f32.tf32.tf32.f32 "         \
                 "{%0,%1,%2,%3}, {%4,%5,%6,%7}, {%8,%9}, {%0,%1,%2,%3};"       \
                 : "+f"(cc[0]), "+f"(cc[1]), "+f"(cc[2]), "+f"(cc[3])          \
                 : "r"(aa[0]), "r"(aa[1]), "r"(aa[2]), "r"(aa[3]),             \
                   "r"(bb[0]), "r"(bb[1]));

// ---------------- 1) tiled local pooling -> ctx ----------------
__global__ __launch_bounds__(256)
void pool_kernel(const float* __restrict__ x, const float* __restrict__ Wl,
                 float* __restrict__ ctx)
{
    __shared__ float xs[4][768];
    __shared__ float red[4][8];
    __shared__ float ws[4];
    int t = blockIdx.x, b = blockIdx.y;
    int tid = threadIdx.x;
    const float* xb = x + (size_t)b * NN * DD;
    float* cout = ctx + ((size_t)b * KK + t) * DD;

    if (t == 0) {
        for (int i = tid; i < 192; i += 256)
            ((float4*)cout)[i] = ((const float4*)xb)[i];
        return;
    }
    int tt = t - 1, ti = tt >> 4, tj = tt & 15;
    int rows[4];
#pragma unroll
    for (int i = 0; i < 4; i++)
        rows[i] = 1 + (ti * 2 + (i >> 1)) * 32 + tj * 2 + (i & 1);

    for (int i = tid; i < 4 * 192; i += 256) {
        int rr = i / 192, seg = i - rr * 192;
        ((float4*)&xs[rr][0])[seg] = ((const float4*)(xb + (size_t)rows[rr] * DD))[seg];
    }
    __syncthreads();

    float p0 = 0.f, p1 = 0.f, p2 = 0.f, p3 = 0.f;
    for (int dm = tid; dm < DD; dm += 256) {
        float wv = Wl[dm];
        p0 = fmaf(xs[0][dm], wv, p0);
        p1 = fmaf(xs[1][dm], wv, p1);
        p2 = fmaf(xs[2][dm], wv, p2);
        p3 = fmaf(xs[3][dm], wv, p3);
    }
#pragma unroll
    for (int off = 16; off; off >>= 1) {
        p0 += __shfl_xor_sync(0xffffffffu, p0, off);
        p1 += __shfl_xor_sync(0xffffffffu, p1, off);
        p2 += __shfl_xor_sync(0xffffffffu, p2, off);
        p3 += __shfl_xor_sync(0xffffffffu, p3, off);
    }
    if ((tid & 31) == 0) {
        int wgi = tid >> 5;
        red[0][wgi] = p0; red[1][wgi] = p1; red[2][wgi] = p2; red[3][wgi] = p3;
    }
    __syncthreads();
    if (tid == 0) {
        float s[4];
#pragma unroll
        for (int i = 0; i < 4; i++) {
            float a = 0.f;
#pragma unroll
            for (int wgi = 0; wgi < 8; wgi++) a += red[i][wgi];
            s[i] = a;
        }
        float mx = fmaxf(fmaxf(s[0], s[1]), fmaxf(s[2], s[3]));
        float e0 = __expf(s[0] - mx), e1 = __expf(s[1] - mx);
        float e2 = __expf(s[2] - mx), e3 = __expf(s[3] - mx);
        float inv = 1.f / (e0 + e1 + e2 + e3);
        ws[0] = e0 * inv; ws[1] = e1 * inv; ws[2] = e2 * inv; ws[3] = e3 * inv;
    }
    __syncthreads();
    for (int dm = tid; dm < DD; dm += 256) {
        cout[dm] = ws[0] * xs[0][dm] + ws[1] * xs[1][dm]
                 + ws[2] * xs[2][dm] + ws[3] * xs[3][dm];
    }
}

// ---------------- 2) tf32 tensor-core NT GEMM ----------------
__global__ __launch_bounds__(256, 1)
void gemm_tf32(const float* __restrict__ A, const float* __restrict__ B,
               float* __restrict__ C, int M, int N, int K,
               const float* __restrict__ bias)
{
    __shared__ __align__(16) unsigned As[2][128][20];
    __shared__ __align__(16) unsigned Bs[2][128][20];

    const int tid  = threadIdx.x;
    const int lane = tid & 31, w = tid >> 5;
    const int g = lane >> 2, t4 = lane & 3;
    const int wm = (w >> 2) * 64;
    const int wn = (w & 3) * 32;
    const int bm = blockIdx.y * 128, bn = blockIdx.x * 128;

    const int lrow = tid >> 2;
    const int lk   = (tid & 3) << 2;

    float c[4][4][4];
#pragma unroll
    for (int i = 0; i < 4; i++)
#pragma unroll
        for (int j = 0; j < 4; j++)
#pragma unroll
            for (int e = 0; e < 4; e++) c[i][j][e] = 0.f;

    float4 pa[2], pb[2];
    const float4 z4 = make_float4(0.f, 0.f, 0.f, 0.f);
    const int nkt = K / 16;

#pragma unroll
    for (int i = 0; i < 2; i++) {
        int ar = bm + lrow + i * 64;
        pa[i] = (ar < M) ? *(const float4*)(A + (size_t)ar * K + lk) : z4;
        int br = bn + lrow + i * 64;
        pb[i] = *(const float4*)(B + (size_t)br * K + lk);
    }
#pragma unroll
    for (int i = 0; i < 2; i++) {
        *(uint4*)&As[0][lrow + i * 64][lk] =
            make_uint4(f2tf(pa[i].x), f2tf(pa[i].y), f2tf(pa[i].z), f2tf(pa[i].w));
        *(uint4*)&Bs[0][lrow + i * 64][lk] =
            make_uint4(f2tf(pb[i].x), f2tf(pb[i].y), f2tf(pb[i].z), f2tf(pb[i].w));
    }
    __syncthreads();

    for (int kt = 0; kt < nkt; kt++) {
        const int buf = kt & 1;
        if (kt + 1 < nkt) {
            const int k0 = (kt + 1) * 16;
#pragma unroll
            for (int i = 0; i < 2; i++) {
                int ar = bm + lrow + i * 64;
                pa[i] = (ar < M) ? *(const float4*)(A + (size_t)ar * K + k0 + lk) : z4;
                int br = bn + lrow + i * 64;
                pb[i] = *(const float4*)(B + (size_t)br * K + k0 + lk);
            }
        }
#pragma unroll
        for (int ks = 0; ks < 2; ks++) {
            const int kk = ks * 8;
            unsigned af[4][4], bf[4][2];
#pragma unroll
            for (int i = 0; i < 4; i++) {
                int r = wm + i * 16 + g;
                af[i][0] = As[buf][r    ][kk + t4];
                af[i][1] = As[buf][r + 8][kk + t4];
                af[i][2] = As[buf][r    ][kk + t4 + 4];
                af[i][3] = As[buf][r + 8][kk + t4 + 4];
            }
#pragma unroll
            for (int j = 0; j < 4; j++) {
                int r = wn + j * 8 + g;
                bf[j][0] = Bs[buf][r][kk + t4];
                bf[j][1] = Bs[buf][r][kk + t4 + 4];
            }
#pragma unroll
            for (int i = 0; i < 4; i++)
#pragma unroll
                for (int j = 0; j < 4; j++)
                    MMA_TF32(c[i][j], af[i], bf[j]);
        }
        if (kt + 1 < nkt) {
            const int nb = buf ^ 1;
#pragma unroll
            for (int i = 0; i < 2; i++) {
                *(uint4*)&As[nb][lrow + i * 64][lk] =
                    make_uint4(f2tf(pa[i].x), f2tf(pa[i].y), f2tf(pa[i].z), f2tf(pa[i].w));
                *(uint4*)&Bs[nb][lrow + i * 64][lk] =
                    make_uint4(f2tf(pb[i].x), f2tf(pb[i].y), f2tf(pb[i].z), f2tf(pb[i].w));
            }
            __syncthreads();
        }
    }

#pragma unroll
    for (int j = 0; j < 4; j++) {
        const int col = bn + wn + j * 8 + t4 * 2;
        float b0 = bias ? bias[col] : 0.f;
        float b1 = bias ? bias[col + 1] : 0.f;
#pragma unroll
        for (int i = 0; i < 4; i++) {
            int r0 = bm + wm + i * 16 + g;
            if (r0 < M)
                *(float2*)(C + (size_t)r0 * N + col) =
                    make_float2(c[i][j][0] + b0, c[i][j][1] + b1);
            int r1 = r0 + 8;
            if (r1 < M)
                *(float2*)(C + (size_t)r1 * N + col) =
                    make_float2(c[i][j][2] + b0, c[i][j][3] + b1);
        }
    }
}

// ---------------- 3) CPB relative-position bias ----------------
__global__ __launch_bounds__(128)
void cpb_kernel(const float* __restrict__ feats, const float* __restrict__ mask,
                const float* __restrict__ w1, const float* __restrict__ b1,
                const float* __restrict__ w2, const float* __restrict__ b2,
                float* __restrict__ bias)
{
    int idx = blockIdx.x * blockDim.x + threadIdx.x;
    if (idx >= NK) return;
    float f0 = feats[2 * idx], f1 = feats[2 * idx + 1];
    float m = mask[idx];
    float h[32];
#pragma unroll
    for (int c = 0; c < 32; c++) {
        float t = fmaf(f0, w1[2 * c], fmaf(f1, w1[2 * c + 1], b1[c]));
        h[c] = 0.5f * t * (1.f + erff(t * 0.7071067811865475f));
    }
#pragma unroll
    for (int hh = 0; hh < HH; hh++) {
        float s = b2[hh];
#pragma unroll
        for (int c = 0; c < 32; c++) s = fmaf(w2[hh * 32 + c], h[c], s);
        bias[(size_t)hh * NK + idx] = s * m;
    }
}

// ---------------- 4) mma flash attention ----------------
// block = 128 queries x one (b,h); 8 warps, each owns an m16 row slab.
// S kept entirely in accum registers (33 m16n8 tiles over 264 padded keys).
#define QT   128
#define KP   264
#define NJT  33     // KP/8
#define QSTR 68
#define KSTR 68
#define VSTR 72

__global__ __launch_bounds__(256, 1)
void attn_mma(const float* __restrict__ q, const float* __restrict__ kv,
              const float* __restrict__ bias, float* __restrict__ o)
{
    extern __shared__ unsigned smu[];
    unsigned* Qs = smu;                       // [128][68]
    unsigned* Ks = Qs + QT * QSTR;            // [264][68]
    unsigned* Vs = Ks + KP * KSTR;            // [264][72]

    const int qb0 = blockIdx.x * QT;
    const int h = blockIdx.y, b = blockIdx.z;
    const int tid = threadIdx.x, w = tid >> 5, lane = tid & 31;
    const int g = lane >> 2, t4 = lane & 3;
    const float4 z4 = make_float4(0.f, 0.f, 0.f, 0.f);

    // ---- stage Q (tf32) ----
    const float* qbase = q + (size_t)b * NN * DD + (size_t)h * 64;
    for (int i = tid; i < QT * 16; i += 256) {
        int r = i >> 4, seg = i & 15;
        int n = qb0 + r;
        float4 v = (n < NN) ? *(const float4*)(qbase + (size_t)n * DD + seg * 4) : z4;
        unsigned* dst = Qs + r * QSTR + seg * 4;
        dst[0] = f2tf(v.x); dst[1] = f2tf(v.y); dst[2] = f2tf(v.z); dst[3] = f2tf(v.w);
    }
    // ---- stage K, V (tf32) ----
    const float* kbase = kv + (size_t)b * KK * (2 * DD) + (size_t)h * 64;
    for (int i = tid; i < KP * 16; i += 256) {
        int r = i >> 4, seg = i & 15;
        float4 kvv = z4, vvv = z4;
        if (r < KK) {
            kvv = *(const float4*)(kbase + (size_t)r * (2 * DD) + seg * 4);
            vvv = *(const float4*)(kbase + (size_t)r * (2 * DD) + DD + seg * 4);
        }
        unsigned* kd = Ks + r * KSTR + seg * 4;
        kd[0] = f2tf(kvv.x); kd[1] = f2tf(kvv.y); kd[2] = f2tf(kvv.z); kd[3] = f2tf(kvv.w);
        unsigned* vd = Vs + r * VSTR + seg * 4;
        vd[0] = f2tf(vvv.x); vd[1] = f2tf(vvv.y); vd[2] = f2tf(vvv.z); vd[3] = f2tf(vvv.w);
    }
    __syncthreads();

    // ---- QK^T : S[16 x 264] per warp ----
    const int wq = w * 16;
    unsigned aq[8][4];
#pragma unroll
    for (int kt = 0; kt < 8; kt++) {
        int kk = kt * 8;
        aq[kt][0] = Qs[(wq + g    ) * QSTR + kk + t4];
        aq[kt][1] = Qs[(wq + g + 8) * QSTR + kk + t4];
        aq[kt][2] = Qs[(wq + g    ) * QSTR + kk + t4 + 4];
        aq[kt][3] = Qs[(wq + g + 8) * QSTR + kk + t4 + 4];
    }

    float s[NJT][4];
#pragma unroll
    for (int j = 0; j < NJT; j++) {
        s[j][0] = s[j][1] = s[j][2] = s[j][3] = 0.f;
#pragma unroll
        for (int kt = 0; kt < 8; kt++) {
            unsigned bf[2];
            const unsigned* kp = Ks + (j * 8 + g) * KSTR + kt * 8 + t4;
            bf[0] = kp[0];
            bf[1] = kp[4];
            MMA_TF32(s[j], aq[kt], bf);
        }
    }

    // ---- scale + bias (accumulator layout: rows g,g+8; cols 2t4,2t4+1) ----
    const int nrow0 = qb0 + wq + g;
    const int nrow1 = nrow0 + 8;
    const float* bp0 = bias + ((size_t)h * NN + (nrow0 < NN ? nrow0 : NN - 1)) * KK;
    const float* bp1 = bias + ((size_t)h * NN + (nrow1 < NN ? nrow1 : NN - 1)) * KK;
#pragma unroll
    for (int j = 0; j < NJT; j++) {
        int k0 = j * 8 + 2 * t4;
        s[j][0] = (k0     < KK) ? fmaf(s[j][0], 0.125f, bp0[k0])     : -1e30f;
        s[j][1] = (k0 + 1 < KK) ? fmaf(s[j][1], 0.125f, bp0[k0 + 1]) : -1e30f;
        s[j][2] = (k0     < KK) ? fmaf(s[j][2], 0.125f, bp1[k0])     : -1e30f;
        s[j][3] = (k0 + 1 < KK) ? fmaf(s[j][3], 0.125f, bp1[k0 + 1]) : -1e30f;
    }

    // ---- row softmax (reduce across the 4 lanes sharing a row) ----
    float m0 = -1e30f, m1 = -1e30f;
#pragma unroll
    for (int j = 0; j < NJT; j++) {
        m0 = fmaxf(m0, fmaxf(s[j][0], s[j][1]));
        m1 = fmaxf(m1, fmaxf(s[j][2], s[j][3]));
    }
    m0 = fmaxf(m0, __shfl_xor_sync(0xffffffffu, m0, 1));
    m0 = fmaxf(m0, __shfl_xor_sync(0xffffffffu, m0, 2));
    m1 = fmaxf(m1, __shfl_xor_sync(0xffffffffu, m1, 1));
    m1 = fmaxf(m1, __shfl_xor_sync(0xffffffffu, m1, 2));

    float l0 = 0.f, l1 = 0.f;
#pragma unroll
    for (int j = 0; j < NJT; j++) {
        s[j][0] = __expf(s[j][0] - m0); l0 += s[j][0];
        s[j][1] = __expf(s[j][1] - m0); l0 += s[j][1];
        s[j][2] = __expf(s[j][2] - m1); l1 += s[j][2];
        s[j][3] = __expf(s[j][3] - m1); l1 += s[j][3];
    }
    l0 += __shfl_xor_sync(0xffffffffu, l0, 1);
    l0 += __shfl_xor_sync(0xffffffffu, l0, 2);
    l1 += __shfl_xor_sync(0xffffffffu, l1, 1);
    l1 += __shfl_xor_sync(0xffffffffu, l1, 2);

    // ---- P @ V : convert accum fragment -> A fragment via shuffles ----
    float ov[8][4];
#pragma unroll
    for (int t = 0; t < 8; t++)
        ov[t][0] = ov[t][1] = ov[t][2] = ov[t][3] = 0.f;

    const int src0 = (lane & ~3) | (t4 >> 1);
    const int src2 = src0 + 2;
    const bool odd = (t4 & 1);
#pragma unroll
    for (int j = 0; j < NJT; j++) {
        float v00 = __shfl_sync(0xffffffffu, s[j][0], src0);
        float v01 = __shfl_sync(0xffffffffu, s[j][1], src0);
        float v20 = __shfl_sync(0xffffffffu, s[j][2], src0);
        float v21 = __shfl_sync(0xffffffffu, s[j][3], src0);
        float w00 = __shfl_sync(0xffffffffu, s[j][0], src2);
        float w01 = __shfl_sync(0xffffffffu, s[j][1], src2);
        float w20 = __shfl_sync(0xffffffffu, s[j][2], src2);
        float w21 = __shfl_sync(0xffffffffu, s[j][3], src2);
        unsigned ap[4];
        ap[0] = f2tf(odd ? v01 : v00);   // P[g][t4]
        ap[1] = f2tf(odd ? v21 : v20);   // P[g+8][t4]
        ap[2] = f2tf(odd ? w01 : w00);   // P[g][t4+4]
        ap[3] = f2tf(odd ? w21 : w20);   // P[g+8][t4+4]
#pragma unroll
        for (int t = 0; t < 8; t++) {
            unsigned bf[2];
            const unsigned* vp = Vs + (j * 8 + t4) * VSTR + t * 8 + g;
            bf[0] = vp[0];
            bf[1] = vp[4 * VSTR];
            MMA_TF32(ov[t], ap, bf);
        }
    }

    // ---- epilogue: normalize & store ----
    const float inv0 = 1.f / l0, inv1 = 1.f / l1;
#pragma unroll
    for (int t = 0; t < 8; t++) {
        int col = h * 64 + t * 8 + 2 * t4;
        if (nrow0 < NN)
            *(float2*)(o + ((size_t)b * NN + nrow0) * DD + col) =
                make_float2(ov[t][0] * inv0, ov[t][1] * inv0);
        if (nrow1 < NN)
            *(float2*)(o + ((size_t)b * NN + nrow1) * DD + col) =
                make_float2(ov[t][2] * inv1, ov[t][3] * inv1);
    }
}

// ---------------- launch ----------------
extern "C" void kernel_launch(void* const* d_in, const int* in_sizes, int n_in,
                              void* d_out, int out_size)
{
    const float* x     = (const float*)d_in[0];
    const float* Wl    = (const float*)d_in[1];
    const float* Wq    = (const float*)d_in[2];
    const float* Wkv   = (const float*)d_in[3];
    const float* Wo    = (const float*)d_in[4];
    const float* bo    = (const float*)d_in[5];
    const float* w1    = (const float*)d_in[6];
    const float* b1    = (const float*)d_in[7];
    const float* w2    = (const float*)d_in[8];
    const float* b2    = (const float*)d_in[9];
    const float* feats = (const float*)d_in[10];
    const float* mask  = (const float*)d_in[11];
    float* out = (float*)d_out;

    float *ctx, *qb, *kvb, *biasb, *ob;
    cudaGetSymbolAddress((void**)&ctx,   g_ctx);
    cudaGetSymbolAddress((void**)&qb,    g_q);
    cudaGetSymbolAddress((void**)&kvb,   g_kv);
    cudaGetSymbolAddress((void**)&biasb, g_bias);
    cudaGetSymbolAddress((void**)&ob,    g_o);

    const int ATTN_SMEM = (QT * QSTR + KP * KSTR + KP * VSTR) * 4; // 182656 B
    cudaFuncSetAttribute(attn_mma, cudaFuncAttributeMaxDynamicSharedMemorySize,
                         ATTN_SMEM);

    // 1. pooled context (tile 0 = register-token copy)
    pool_kernel<<<dim3(KK, BB), 256>>>(x, Wl, ctx);
    // 2. Q = x @ Wq^T    [32800,768]
    gemm_tf32<<<dim3(6, 257), 256>>>(x, Wq, qb, BB * NN, DD, DD, nullptr);
    // 3. KV = ctx @ Wkv^T [8224,1536]
    gemm_tf32<<<dim3(12, 65), 256>>>(ctx, Wkv, kvb, BB * KK, 2 * DD, DD, nullptr);
    // 4. CPB bias [12,1025,257]
    cpb_kernel<<<(NK + 127) / 128, 128>>>(feats, mask, w1, b1, w2, b2, biasb);
    // 5. mma attention
    attn_mma<<<dim3((NN + QT - 1) / QT, HH, BB), 256, ATTN_SMEM>>>(qb, kvb, biasb, ob);
    // 6. out = o @ Wo^T + bo
    gemm_tf32<<<dim3(6, 257), 256>>>(ob, Wo, out, BB * NN, DD, DD, bo);
}

// round 10
// speedup vs baseline: 3.1270x; 1.2129x over previous
#include <cuda_runtime.h>
#include <math.h>

#define BB 32
#define NN 1025
#define DD 768
#define HH 12
#define KK 257   // context length
#define NK (NN*KK)

// ---------------- scratch (device globals; no allocs allowed) ----------------
__device__ float g_ctx [BB * KK * DD];        // [B,257,768]
__device__ float g_q   [BB * NN * DD];        // [B,1025,768]
__device__ float g_kv  [BB * KK * 2 * DD];    // [B,257,1536]  (k | v)
__device__ float g_bias[HH * NN * KK];        // [12,1025,257]
__device__ float g_o   [BB * NN * DD];        // [B,1025,768]

// ---------------- helpers ----------------
__device__ __forceinline__ unsigned f2tf(float f) {
    unsigned u; asm("cvt.rna.tf32.f32 %0, %1;" : "=r"(u) : "f"(f)); return u;
}

#define MMA_TF32(cc, aa, bb)                                                   \
    asm volatile("mma.sync.aligned.m16n8k8.row.col.f32.tf32.tf32.f32 "         \
                 "{%0,%1,%2,%3}, {%4,%5,%6,%7}, {%8,%9}, {%0,%1,%2,%3};"       \
                 : "+f"(cc[0]), "+f"(cc[1]), "+f"(cc[2]), "+f"(cc[3])          \
                 : "r"(aa[0]), "r"(aa[1]), "r"(aa[2]), "r"(aa[3]),             \
                   "r"(bb[0]), "r"(bb[1]));

// ---------------- 1) tiled local pooling -> ctx ----------------
__global__ __launch_bounds__(256)
void pool_kernel(const float* __restrict__ x, const float* __restrict__ Wl,
                 float* __restrict__ ctx)
{
    __shared__ float xs[4][768];
    __shared__ float red[4][8];
    __shared__ float ws[4];
    int t = blockIdx.x, b = blockIdx.y;
    int tid = threadIdx.x;
    const float* xb = x + (size_t)b * NN * DD;
    float* cout = ctx + ((size_t)b * KK + t) * DD;

    if (t == 0) {
        for (int i = tid; i < 192; i += 256)
            ((float4*)cout)[i] = ((const float4*)xb)[i];
        return;
    }
    int tt = t - 1, ti = tt >> 4, tj = tt & 15;
    int rows[4];
#pragma unroll
    for (int i = 0; i < 4; i++)
        rows[i] = 1 + (ti * 2 + (i >> 1)) * 32 + tj * 2 + (i & 1);

    for (int i = tid; i < 4 * 192; i += 256) {
        int rr = i / 192, seg = i - rr * 192;
        ((float4*)&xs[rr][0])[seg] = ((const float4*)(xb + (size_t)rows[rr] * DD))[seg];
    }
    __syncthreads();

    float p0 = 0.f, p1 = 0.f, p2 = 0.f, p3 = 0.f;
    for (int dm = tid; dm < DD; dm += 256) {
        float wv = Wl[dm];
        p0 = fmaf(xs[0][dm], wv, p0);
        p1 = fmaf(xs[1][dm], wv, p1);
        p2 = fmaf(xs[2][dm], wv, p2);
        p3 = fmaf(xs[3][dm], wv, p3);
    }
#pragma unroll
    for (int off = 16; off; off >>= 1) {
        p0 += __shfl_xor_sync(0xffffffffu, p0, off);
        p1 += __shfl_xor_sync(0xffffffffu, p1, off);
        p2 += __shfl_xor_sync(0xffffffffu, p2, off);
        p3 += __shfl_xor_sync(0xffffffffu, p3, off);
    }
    if ((tid & 31) == 0) {
        int wgi = tid >> 5;
        red[0][wgi] = p0; red[1][wgi] = p1; red[2][wgi] = p2; red[3][wgi] = p3;
    }
    __syncthreads();
    if (tid == 0) {
        float s[4];
#pragma unroll
        for (int i = 0; i < 4; i++) {
            float a = 0.f;
#pragma unroll
            for (int wgi = 0; wgi < 8; wgi++) a += red[i][wgi];
            s[i] = a;
        }
        float mx = fmaxf(fmaxf(s[0], s[1]), fmaxf(s[2], s[3]));
        float e0 = __expf(s[0] - mx), e1 = __expf(s[1] - mx);
        float e2 = __expf(s[2] - mx), e3 = __expf(s[3] - mx);
        float inv = 1.f / (e0 + e1 + e2 + e3);
        ws[0] = e0 * inv; ws[1] = e1 * inv; ws[2] = e2 * inv; ws[3] = e3 * inv;
    }
    __syncthreads();
    for (int dm = tid; dm < DD; dm += 256) {
        cout[dm] = ws[0] * xs[0][dm] + ws[1] * xs[1][dm]
                 + ws[2] * xs[2][dm] + ws[3] * xs[3][dm];
    }
}

// ---------------- 2) tf32 tensor-core NT GEMM (occ=2 for latency hiding) ----
__global__ __launch_bounds__(256, 2)
void gemm_tf32(const float* __restrict__ A, const float* __restrict__ B,
               float* __restrict__ C, int M, int N, int K,
               const float* __restrict__ bias)
{
    __shared__ __align__(16) unsigned As[2][128][20];
    __shared__ __align__(16) unsigned Bs[2][128][20];

    const int tid  = threadIdx.x;
    const int lane = tid & 31, w = tid >> 5;
    const int g = lane >> 2, t4 = lane & 3;
    const int wm = (w >> 2) * 64;
    const int wn = (w & 3) * 32;
    const int bm = blockIdx.y * 128, bn = blockIdx.x * 128;

    const int lrow = tid >> 2;
    const int lk   = (tid & 3) << 2;

    float c[4][4][4];
#pragma unroll
    for (int i = 0; i < 4; i++)
#pragma unroll
        for (int j = 0; j < 4; j++)
#pragma unroll
            for (int e = 0; e < 4; e++) c[i][j][e] = 0.f;

    float4 pa[2], pb[2];
    const float4 z4 = make_float4(0.f, 0.f, 0.f, 0.f);
    const int nkt = K / 16;

#pragma unroll
    for (int i = 0; i < 2; i++) {
        int ar = bm + lrow + i * 64;
        pa[i] = (ar < M) ? *(const float4*)(A + (size_t)ar * K + lk) : z4;
        int br = bn + lrow + i * 64;
        pb[i] = *(const float4*)(B + (size_t)br * K + lk);
    }
#pragma unroll
    for (int i = 0; i < 2; i++) {
        *(uint4*)&As[0][lrow + i * 64][lk] =
            make_uint4(f2tf(pa[i].x), f2tf(pa[i].y), f2tf(pa[i].z), f2tf(pa[i].w));
        *(uint4*)&Bs[0][lrow + i * 64][lk] =
            make_uint4(f2tf(pb[i].x), f2tf(pb[i].y), f2tf(pb[i].z), f2tf(pb[i].w));
    }
    __syncthreads();

    for (int kt = 0; kt < nkt; kt++) {
        const int buf = kt & 1;
        if (kt + 1 < nkt) {
            const int k0 = (kt + 1) * 16;
#pragma unroll
            for (int i = 0; i < 2; i++) {
                int ar = bm + lrow + i * 64;
                pa[i] = (ar < M) ? *(const float4*)(A + (size_t)ar * K + k0 + lk) : z4;
                int br = bn + lrow + i * 64;
                pb[i] = *(const float4*)(B + (size_t)br * K + k0 + lk);
            }
        }
#pragma unroll
        for (int ks = 0; ks < 2; ks++) {
            const int kk = ks * 8;
            unsigned af[4][4], bf[4][2];
#pragma unroll
            for (int i = 0; i < 4; i++) {
                int r = wm + i * 16 + g;
                af[i][0] = As[buf][r    ][kk + t4];
                af[i][1] = As[buf][r + 8][kk + t4];
                af[i][2] = As[buf][r    ][kk + t4 + 4];
                af[i][3] = As[buf][r + 8][kk + t4 + 4];
            }
#pragma unroll
            for (int j = 0; j < 4; j++) {
                int r = wn + j * 8 + g;
                bf[j][0] = Bs[buf][r][kk + t4];
                bf[j][1] = Bs[buf][r][kk + t4 + 4];
            }
#pragma unroll
            for (int i = 0; i < 4; i++)
#pragma unroll
                for (int j = 0; j < 4; j++)
                    MMA_TF32(c[i][j], af[i], bf[j]);
        }
        if (kt + 1 < nkt) {
            const int nb = buf ^ 1;
#pragma unroll
            for (int i = 0; i < 2; i++) {
                *(uint4*)&As[nb][lrow + i * 64][lk] =
                    make_uint4(f2tf(pa[i].x), f2tf(pa[i].y), f2tf(pa[i].z), f2tf(pa[i].w));
                *(uint4*)&Bs[nb][lrow + i * 64][lk] =
                    make_uint4(f2tf(pb[i].x), f2tf(pb[i].y), f2tf(pb[i].z), f2tf(pb[i].w));
            }
            __syncthreads();
        }
    }

#pragma unroll
    for (int j = 0; j < 4; j++) {
        const int col = bn + wn + j * 8 + t4 * 2;
        float b0 = bias ? bias[col] : 0.f;
        float b1 = bias ? bias[col + 1] : 0.f;
#pragma unroll
        for (int i = 0; i < 4; i++) {
            int r0 = bm + wm + i * 16 + g;
            if (r0 < M)
                *(float2*)(C + (size_t)r0 * N + col) =
                    make_float2(c[i][j][0] + b0, c[i][j][1] + b1);
            int r1 = r0 + 8;
            if (r1 < M)
                *(float2*)(C + (size_t)r1 * N + col) =
                    make_float2(c[i][j][2] + b0, c[i][j][3] + b1);
        }
    }
}

// ---------------- 3) CPB relative-position bias ----------------
__global__ __launch_bounds__(128)
void cpb_kernel(const float* __restrict__ feats, const float* __restrict__ mask,
                const float* __restrict__ w1, const float* __restrict__ b1,
                const float* __restrict__ w2, const float* __restrict__ b2,
                float* __restrict__ bias)
{
    int idx = blockIdx.x * blockDim.x + threadIdx.x;
    if (idx >= NK) return;
    float f0 = feats[2 * idx], f1 = feats[2 * idx + 1];
    float m = mask[idx];
    float h[32];
#pragma unroll
    for (int c = 0; c < 32; c++) {
        float t = fmaf(f0, w1[2 * c], fmaf(f1, w1[2 * c + 1], b1[c]));
        h[c] = 0.5f * t * (1.f + erff(t * 0.7071067811865475f));
    }
#pragma unroll
    for (int hh = 0; hh < HH; hh++) {
        float s = b2[hh];
#pragma unroll
        for (int c = 0; c < 32; c++) s = fmaf(w2[hh * 32 + c], h[c], s);
        bias[(size_t)hh * NK + idx] = s * m;
    }
}

// ---------------- 4) mma flash attention ----------------
#define QT   128
#define KP   264
#define NJT  33     // KP/8
#define QSTR 68
#define KSTR 68
#define VSTR 72

__global__ __launch_bounds__(256, 1)
void attn_mma(const float* __restrict__ q, const float* __restrict__ kv,
              const float* __restrict__ bias, float* __restrict__ o)
{
    extern __shared__ unsigned smu[];
    unsigned* Qs = smu;                       // [128][68]
    unsigned* Ks = Qs + QT * QSTR;            // [264][68]
    unsigned* Vs = Ks + KP * KSTR;            // [264][72]

    const int qb0 = blockIdx.x * QT;
    const int h = blockIdx.y, b = blockIdx.z;
    const int tid = threadIdx.x, w = tid >> 5, lane = tid & 31;
    const int g = lane >> 2, t4 = lane & 3;
    const float4 z4 = make_float4(0.f, 0.f, 0.f, 0.f);

    // ---- stage Q (tf32) ----
    const float* qbase = q + (size_t)b * NN * DD + (size_t)h * 64;
    for (int i = tid; i < QT * 16; i += 256) {
        int r = i >> 4, seg = i & 15;
        int n = qb0 + r;
        float4 v = (n < NN) ? *(const float4*)(qbase + (size_t)n * DD + seg * 4) : z4;
        unsigned* dst = Qs + r * QSTR + seg * 4;
        dst[0] = f2tf(v.x); dst[1] = f2tf(v.y); dst[2] = f2tf(v.z); dst[3] = f2tf(v.w);
    }
    // ---- stage K, V (tf32) ----
    const float* kbase = kv + (size_t)b * KK * (2 * DD) + (size_t)h * 64;
    for (int i = tid; i < KP * 16; i += 256) {
        int r = i >> 4, seg = i & 15;
        float4 kvv = z4, vvv = z4;
        if (r < KK) {
            kvv = *(const float4*)(kbase + (size_t)r * (2 * DD) + seg * 4);
            vvv = *(const float4*)(kbase + (size_t)r * (2 * DD) + DD + seg * 4);
        }
        unsigned* kd = Ks + r * KSTR + seg * 4;
        kd[0] = f2tf(kvv.x); kd[1] = f2tf(kvv.y); kd[2] = f2tf(kvv.z); kd[3] = f2tf(kvv.w);
        unsigned* vd = Vs + r * VSTR + seg * 4;
        vd[0] = f2tf(vvv.x); vd[1] = f2tf(vvv.y); vd[2] = f2tf(vvv.z); vd[3] = f2tf(vvv.w);
    }
    __syncthreads();

    // ---- QK^T : S[16 x 264] per warp ----
    const int wq = w * 16;
    unsigned aq[8][4];
#pragma unroll
    for (int kt = 0; kt < 8; kt++) {
        int kk = kt * 8;
        aq[kt][0] = Qs[(wq + g    ) * QSTR + kk + t4];
        aq[kt][1] = Qs[(wq + g + 8) * QSTR + kk + t4];
        aq[kt][2] = Qs[(wq + g    ) * QSTR + kk + t4 + 4];
        aq[kt][3] = Qs[(wq + g + 8) * QSTR + kk + t4 + 4];
    }

    float s[NJT][4];
#pragma unroll
    for (int j = 0; j < NJT; j++) {
        s[j][0] = s[j][1] = s[j][2] = s[j][3] = 0.f;
#pragma unroll
        for (int kt = 0; kt < 8; kt++) {
            unsigned bf[2];
            const unsigned* kp = Ks + (j * 8 + g) * KSTR + kt * 8 + t4;
            bf[0] = kp[0];
            bf[1] = kp[4];
            MMA_TF32(s[j], aq[kt], bf);
        }
    }

    // ---- scale + bias (accumulator layout: rows g,g+8; cols 2t4,2t4+1) ----
    const int nrow0 = qb0 + wq + g;
    const int nrow1 = nrow0 + 8;
    const float* bp0 = bias + ((size_t)h * NN + (nrow0 < NN ? nrow0 : NN - 1)) * KK;
    const float* bp1 = bias + ((size_t)h * NN + (nrow1 < NN ? nrow1 : NN - 1)) * KK;
#pragma unroll
    for (int j = 0; j < NJT; j++) {
        int k0 = j * 8 + 2 * t4;
        s[j][0] = (k0     < KK) ? fmaf(s[j][0], 0.125f, bp0[k0])     : -1e30f;
        s[j][1] = (k0 + 1 < KK) ? fmaf(s[j][1], 0.125f, bp0[k0 + 1]) : -1e30f;
        s[j][2] = (k0     < KK) ? fmaf(s[j][2], 0.125f, bp1[k0])     : -1e30f;
        s[j][3] = (k0 + 1 < KK) ? fmaf(s[j][3], 0.125f, bp1[k0 + 1]) : -1e30f;
    }

    // ---- row softmax (reduce across the 4 lanes sharing a row) ----
    float m0 = -1e30f, m1 = -1e30f;
#pragma unroll
    for (int j = 0; j < NJT; j++) {
        m0 = fmaxf(m0, fmaxf(s[j][0], s[j][1]));
        m1 = fmaxf(m1, fmaxf(s[j][2], s[j][3]));
    }
    m0 = fmaxf(m0, __shfl_xor_sync(0xffffffffu, m0, 1));
    m0 = fmaxf(m0, __shfl_xor_sync(0xffffffffu, m0, 2));
    m1 = fmaxf(m1, __shfl_xor_sync(0xffffffffu, m1, 1));
    m1 = fmaxf(m1, __shfl_xor_sync(0xffffffffu, m1, 2));

    float l0 = 0.f, l1 = 0.f;
#pragma unroll
    for (int j = 0; j < NJT; j++) {
        s[j][0] = __expf(s[j][0] - m0); l0 += s[j][0];
        s[j][1] = __expf(s[j][1] - m0); l0 += s[j][1];
        s[j][2] = __expf(s[j][2] - m1); l1 += s[j][2];
        s[j][3] = __expf(s[j][3] - m1); l1 += s[j][3];
    }
    l0 += __shfl_xor_sync(0xffffffffu, l0, 1);
    l0 += __shfl_xor_sync(0xffffffffu, l0, 2);
    l1 += __shfl_xor_sync(0xffffffffu, l1, 1);
    l1 += __shfl_xor_sync(0xffffffffu, l1, 2);

    // ---- P @ V : convert accum fragment -> A fragment via shuffles ----
    float ov[8][4];
#pragma unroll
    for (int t = 0; t < 8; t++)
        ov[t][0] = ov[t][1] = ov[t][2] = ov[t][3] = 0.f;

    const int src0 = (lane & ~3) | (t4 >> 1);
    const int src2 = src0 + 2;
    const bool odd = (t4 & 1);
#pragma unroll
    for (int j = 0; j < NJT; j++) {
        float v00 = __shfl_sync(0xffffffffu, s[j][0], src0);
        float v01 = __shfl_sync(0xffffffffu, s[j][1], src0);
        float v20 = __shfl_sync(0xffffffffu, s[j][2], src0);
        float v21 = __shfl_sync(0xffffffffu, s[j][3], src0);
        float w00 = __shfl_sync(0xffffffffu, s[j][0], src2);
        float w01 = __shfl_sync(0xffffffffu, s[j][1], src2);
        float w20 = __shfl_sync(0xffffffffu, s[j][2], src2);
        float w21 = __shfl_sync(0xffffffffu, s[j][3], src2);
        unsigned ap[4];
        ap[0] = f2tf(odd ? v01 : v00);   // P[g][t4]
        ap[1] = f2tf(odd ? v21 : v20);   // P[g+8][t4]
        ap[2] = f2tf(odd ? w01 : w00);   // P[g][t4+4]
        ap[3] = f2tf(odd ? w21 : w20);   // P[g+8][t4+4]
#pragma unroll
        for (int t = 0; t < 8; t++) {
            unsigned bf[2];
            const unsigned* vp = Vs + (j * 8 + t4) * VSTR + t * 8 + g;
            bf[0] = vp[0];
            bf[1] = vp[4 * VSTR];
            MMA_TF32(ov[t], ap, bf);
        }
    }

    // ---- epilogue: normalize & store ----
    const float inv0 = 1.f / l0, inv1 = 1.f / l1;
#pragma unroll
    for (int t = 0; t < 8; t++) {
        int col = h * 64 + t * 8 + 2 * t4;
        if (nrow0 < NN)
            *(float2*)(o + ((size_t)b * NN + nrow0) * DD + col) =
                make_float2(ov[t][0] * inv0, ov[t][1] * inv0);
        if (nrow1 < NN)
            *(float2*)(o + ((size_t)b * NN + nrow1) * DD + col) =
                make_float2(ov[t][2] * inv1, ov[t][3] * inv1);
    }
}

// ---------------- launch ----------------
extern "C" void kernel_launch(void* const* d_in, const int* in_sizes, int n_in,
                              void* d_out, int out_size)
{
    const float* x     = (const float*)d_in[0];
    const float* Wl    = (const float*)d_in[1];
    const float* Wq    = (const float*)d_in[2];
    const float* Wkv   = (const float*)d_in[3];
    const float* Wo    = (const float*)d_in[4];
    const float* bo    = (const float*)d_in[5];
    const float* w1    = (const float*)d_in[6];
    const float* b1    = (const float*)d_in[7];
    const float* w2    = (const float*)d_in[8];
    const float* b2    = (const float*)d_in[9];
    const float* feats = (const float*)d_in[10];
    const float* mask  = (const float*)d_in[11];
    float* out = (float*)d_out;

    float *ctx, *qb, *kvb, *biasb, *ob;
    cudaGetSymbolAddress((void**)&ctx,   g_ctx);
    cudaGetSymbolAddress((void**)&qb,    g_q);
    cudaGetSymbolAddress((void**)&kvb,   g_kv);
    cudaGetSymbolAddress((void**)&biasb, g_bias);
    cudaGetSymbolAddress((void**)&ob,    g_o);

    const int ATTN_SMEM = (QT * QSTR + KP * KSTR + KP * VSTR) * 4; // 182656 B
    cudaFuncSetAttribute(attn_mma, cudaFuncAttributeMaxDynamicSharedMemorySize,
                         ATTN_SMEM);

    // 1. pooled context (tile 0 = register-token copy)
    pool_kernel<<<dim3(KK, BB), 256>>>(x, Wl, ctx);
    // 2. Q = x @ Wq^T    [32800,768]
    gemm_tf32<<<dim3(6, 257), 256>>>(x, Wq, qb, BB * NN, DD, DD, nullptr);
    // 3. KV = ctx @ Wkv^T [8224,1536]
    gemm_tf32<<<dim3(12, 65), 256>>>(ctx, Wkv, kvb, BB * KK, 2 * DD, DD, nullptr);
    // 4. CPB bias [12,1025,257]
    cpb_kernel<<<(NK + 127) / 128, 128>>>(feats, mask, w1, b1, w2, b2, biasb);
    // 5. mma attention
    attn_mma<<<dim3((NN + QT - 1) / QT, HH, BB), 256, ATTN_SMEM>>>(qb, kvb, biasb, ob);
    // 6. out = o @ Wo^T + bo
    gemm_tf32<<<dim3(6, 257), 256>>>(ob, Wo, out, BB * NN, DD, DD, bo);
}

// round 13
// speedup vs baseline: 3.4192x; 1.0934x over previous
#include <cuda_runtime.h>
#include <math.h>

#define BB 32
#define NN 1025
#define DD 768
#define HH 12
#define KK 257   // context length
#define NK (NN*KK)

// ---------------- scratch (device globals; no allocs allowed) ----------------
__device__ float g_ctx [BB * KK * DD];        // [B,257,768]
__device__ float g_q   [BB * NN * DD];        // [B,1025,768]
__device__ float g_kv  [BB * KK * 2 * DD];    // [B,257,1536]  (k | v)
__device__ float g_bias[HH * NN * KK];        // [12,1025,257]
__device__ float g_o   [BB * NN * DD];        // [B,1025,768]

// ---------------- helpers ----------------
__device__ __forceinline__ unsigned f2tf(float f) {
    unsigned u; asm("cvt.rna.tf32.f32 %0, %1;" : "=r"(u) : "f"(f)); return u;
}

#define MMA_TF32(cc, aa, bb)                                                   \
    asm volatile("mma.sync.aligned.m16n8k8.row.col.f32.tf32.tf32.f32 "         \
                 "{%0,%1,%2,%3}, {%4,%5,%6,%7}, {%8,%9}, {%0,%1,%2,%3};"       \
                 : "+f"(cc[0]), "+f"(cc[1]), "+f"(cc[2]), "+f"(cc[3])          \
                 : "r"(aa[0]), "r"(aa[1]), "r"(aa[2]), "r"(aa[3]),             \
                   "r"(bb[0]), "r"(bb[1]));

__device__ __forceinline__ void cp16(float* smem_dst, const float* gsrc, bool pred) {
    unsigned sa = (unsigned)__cvta_generic_to_shared(smem_dst);
    int sz = pred ? 16 : 0;
    asm volatile("cp.async.cg.shared.global [%0], [%1], 16, %2;"
                 :: "r"(sa), "l"(gsrc), "r"(sz));
}
#define CP_COMMIT() asm volatile("cp.async.commit_group;")
#define CP_WAIT2()  asm volatile("cp.async.wait_group 2;")

// ---------------- 1) tiled local pooling -> ctx ----------------
__global__ __launch_bounds__(256)
void pool_kernel(const float* __restrict__ x, const float* __restrict__ Wl,
                 float* __restrict__ ctx)
{
    __shared__ float xs[4][768];
    __shared__ float red[4][8];
    __shared__ float ws[4];
    int t = blockIdx.x, b = blockIdx.y;
    int tid = threadIdx.x;
    const float* xb = x + (size_t)b * NN * DD;
    float* cout = ctx + ((size_t)b * KK + t) * DD;

    if (t == 0) {
        for (int i = tid; i < 192; i += 256)
            ((float4*)cout)[i] = ((const float4*)xb)[i];
        return;
    }
    int tt = t - 1, ti = tt >> 4, tj = tt & 15;
    int rows[4];
#pragma unroll
    for (int i = 0; i < 4; i++)
        rows[i] = 1 + (ti * 2 + (i >> 1)) * 32 + tj * 2 + (i & 1);

    for (int i = tid; i < 4 * 192; i += 256) {
        int rr = i / 192, seg = i - rr * 192;
        ((float4*)&xs[rr][0])[seg] = ((const float4*)(xb + (size_t)rows[rr] * DD))[seg];
    }
    __syncthreads();

    float p0 = 0.f, p1 = 0.f, p2 = 0.f, p3 = 0.f;
    for (int dm = tid; dm < DD; dm += 256) {
        float wv = Wl[dm];
        p0 = fmaf(xs[0][dm], wv, p0);
        p1 = fmaf(xs[1][dm], wv, p1);
        p2 = fmaf(xs[2][dm], wv, p2);
        p3 = fmaf(xs[3][dm], wv, p3);
    }
#pragma unroll
    for (int off = 16; off; off >>= 1) {
        p0 += __shfl_xor_sync(0xffffffffu, p0, off);
        p1 += __shfl_xor_sync(0xffffffffu, p1, off);
        p2 += __shfl_xor_sync(0xffffffffu, p2, off);
        p3 += __shfl_xor_sync(0xffffffffu, p3, off);
    }
    if ((tid & 31) == 0) {
        int wgi = tid >> 5;
        red[0][wgi] = p0; red[1][wgi] = p1; red[2][wgi] = p2; red[3][wgi] = p3;
    }
    __syncthreads();
    if (tid == 0) {
        float s[4];
#pragma unroll
        for (int i = 0; i < 4; i++) {
            float a = 0.f;
#pragma unroll
            for (int wgi = 0; wgi < 8; wgi++) a += red[i][wgi];
            s[i] = a;
        }
        float mx = fmaxf(fmaxf(s[0], s[1]), fmaxf(s[2], s[3]));
        float e0 = __expf(s[0] - mx), e1 = __expf(s[1] - mx);
        float e2 = __expf(s[2] - mx), e3 = __expf(s[3] - mx);
        float inv = 1.f / (e0 + e1 + e2 + e3);
        ws[0] = e0 * inv; ws[1] = e1 * inv; ws[2] = e2 * inv; ws[3] = e3 * inv;
    }
    __syncthreads();
    for (int dm = tid; dm < DD; dm += 256) {
        cout[dm] = ws[0] * xs[0][dm] + ws[1] * xs[1][dm]
                 + ws[2] * xs[2][dm] + ws[3] * xs[3][dm];
    }
}

// ---------------- 2) tf32 NT GEMM: 4-stage cp.async pipeline, occ=2 --------
// C[m,n] = sum_k A[m,k]*B[n,k] (+bias[n]); 128x128 tile, BK=16.
// Raw fp32 staged via cp.async; cvt.rna.tf32 applied at fragment load.
// A region: 4*128*20 = 10240 floats; B region starts at float 10240.
#define AS(s,r,k) gsm[(((s) * 128 + (r)) * 20) + (k)]
#define BS(s,r,k) gsm[10240 + (((s) * 128 + (r)) * 20) + (k)]

__global__ __launch_bounds__(256, 2)
void gemm_tf32(const float* __restrict__ A, const float* __restrict__ B,
               float* __restrict__ C, int M, int N, int K,
               const float* __restrict__ bias)
{
    extern __shared__ __align__(16) float gsm[];   // 2 * 10240 floats = 80KB

    const int tid  = threadIdx.x;
    const int lane = tid & 31, w = tid >> 5;
    const int g = lane >> 2, t4 = lane & 3;
    const int wm = (w >> 2) * 64;
    const int wn = (w & 3) * 32;
    const int bm = blockIdx.y * 128, bn = blockIdx.x * 128;

    const int lrow = tid >> 2;               // 0..63
    const int lk   = (tid & 3) << 2;         // 0,4,8,12

    // A row clamps (rows can exceed M on the last block-row)
    const int ar0 = bm + lrow,      ar1 = bm + lrow + 64;
    const bool av0 = ar0 < M,       av1 = ar1 < M;
    const int ac0 = av0 ? ar0 : 0,  ac1 = av1 ? ar1 : 0;
    const int br0 = bn + lrow,      br1 = bn + lrow + 64;   // always valid

    float c[4][4][4];
#pragma unroll
    for (int i = 0; i < 4; i++)
#pragma unroll
        for (int j = 0; j < 4; j++)
#pragma unroll
            for (int e = 0; e < 4; e++) c[i][j][e] = 0.f;

    const int nkt = K / 16;   // >= 48 always

    // ---- prologue: fill stages 0..2 ----
#pragma unroll
    for (int s = 0; s < 3; s++) {
        const int k0 = s * 16;
        cp16(&AS(s, lrow,      lk), A + (size_t)ac0 * K + k0 + lk, av0);
        cp16(&AS(s, lrow + 64, lk), A + (size_t)ac1 * K + k0 + lk, av1);
        cp16(&BS(s, lrow,      lk), B + (size_t)br0 * K + k0 + lk, true);
        cp16(&BS(s, lrow + 64, lk), B + (size_t)br1 * K + k0 + lk, true);
        CP_COMMIT();
    }

    for (int kt = 0; kt < nkt; kt++) {
        CP_WAIT2();              // group kt complete (<=2 newer pending)
        __syncthreads();
        const int st = kt & 3;

#pragma unroll
        for (int ks = 0; ks < 2; ks++) {
            const int kk = ks * 8;
            unsigned af[4][4], bf[4][2];
#pragma unroll
            for (int i = 0; i < 4; i++) {
                int r = wm + i * 16 + g;
                af[i][0] = f2tf(AS(st, r,     kk + t4));
                af[i][1] = f2tf(AS(st, r + 8, kk + t4));
                af[i][2] = f2tf(AS(st, r,     kk + t4 + 4));
                af[i][3] = f2tf(AS(st, r + 8, kk + t4 + 4));
            }
#pragma unroll
            for (int j = 0; j < 4; j++) {
                int r = wn + j * 8 + g;
                bf[j][0] = f2tf(BS(st, r, kk + t4));
                bf[j][1] = f2tf(BS(st, r, kk + t4 + 4));
            }
#pragma unroll
            for (int i = 0; i < 4; i++)
#pragma unroll
                for (int j = 0; j < 4; j++)
                    MMA_TF32(c[i][j], af[i], bf[j]);
        }

        // prefetch tile kt+3 into stage (kt+3)&3 == (kt-1)&3 (safe: barrier above)
        const int pf = kt + 3;
        if (pf < nkt) {
            const int s = pf & 3, k0 = pf * 16;
            cp16(&AS(s, lrow,      lk), A + (size_t)ac0 * K + k0 + lk, av0);
            cp16(&AS(s, lrow + 64, lk), A + (size_t)ac1 * K + k0 + lk, av1);
            cp16(&BS(s, lrow,      lk), B + (size_t)br0 * K + k0 + lk, true);
            cp16(&BS(s, lrow + 64, lk), B + (size_t)br1 * K + k0 + lk, true);
        }
        CP_COMMIT();             // commit every iter to keep group count aligned
    }

    // ---- epilogue ----
#pragma unroll
    for (int j = 0; j < 4; j++) {
        const int col = bn + wn + j * 8 + t4 * 2;
        float b0 = bias ? bias[col] : 0.f;
        float b1 = bias ? bias[col + 1] : 0.f;
#pragma unroll
        for (int i = 0; i < 4; i++) {
            int r0 = bm + wm + i * 16 + g;
            if (r0 < M)
                *(float2*)(C + (size_t)r0 * N + col) =
                    make_float2(c[i][j][0] + b0, c[i][j][1] + b1);
            int r1 = r0 + 8;
            if (r1 < M)
                *(float2*)(C + (size_t)r1 * N + col) =
                    make_float2(c[i][j][2] + b0, c[i][j][3] + b1);
        }
    }
}
#define GEMM_SMEM (2 * 4 * 128 * 20 * 4)   // 81920 bytes

// ---------------- 3) CPB relative-position bias ----------------
__global__ __launch_bounds__(128)
void cpb_kernel(const float* __restrict__ feats, const float* __restrict__ mask,
                const float* __restrict__ w1, const float* __restrict__ b1,
                const float* __restrict__ w2, const float* __restrict__ b2,
                float* __restrict__ bias)
{
    int idx = blockIdx.x * blockDim.x + threadIdx.x;
    if (idx >= NK) return;
    float f0 = feats[2 * idx], f1 = feats[2 * idx + 1];
    float m = mask[idx];
    float h[32];
#pragma unroll
    for (int c = 0; c < 32; c++) {
        float t = fmaf(f0, w1[2 * c], fmaf(f1, w1[2 * c + 1], b1[c]));
        h[c] = 0.5f * t * (1.f + erff(t * 0.7071067811865475f));
    }
#pragma unroll
    for (int hh = 0; hh < HH; hh++) {
        float s = b2[hh];
#pragma unroll
        for (int c = 0; c < 32; c++) s = fmaf(w2[hh * 32 + c], h[c], s);
        bias[(size_t)hh * NK + idx] = s * m;
    }
}

// ---------------- 4) mma flash attention ----------------
#define QT   128
#define KP   264
#define NJT  33     // KP/8
#define QSTR 68
#define KSTR 68
#define VSTR 72

__global__ __launch_bounds__(256, 1)
void attn_mma(const float* __restrict__ q, const float* __restrict__ kv,
              const float* __restrict__ bias, float* __restrict__ o)
{
    extern __shared__ unsigned smu[];
    unsigned* Qs = smu;                       // [128][68]
    unsigned* Ks = Qs + QT * QSTR;            // [264][68]
    unsigned* Vs = Ks + KP * KSTR;            // [264][72]

    const int qb0 = blockIdx.x * QT;
    const int h = blockIdx.y, b = blockIdx.z;
    const int tid = threadIdx.x, w = tid >> 5, lane = tid & 31;
    const int g = lane >> 2, t4 = lane & 3;
    const float4 z4 = make_float4(0.f, 0.f, 0.f, 0.f);

    // ---- stage Q (tf32) ----
    const float* qbase = q + (size_t)b * NN * DD + (size_t)h * 64;
    for (int i = tid; i < QT * 16; i += 256) {
        int r = i >> 4, seg = i & 15;
        int n = qb0 + r;
        float4 v = (n < NN) ? *(const float4*)(qbase + (size_t)n * DD + seg * 4) : z4;
        unsigned* dst = Qs + r * QSTR + seg * 4;
        dst[0] = f2tf(v.x); dst[1] = f2tf(v.y); dst[2] = f2tf(v.z); dst[3] = f2tf(v.w);
    }
    // ---- stage K, V (tf32) ----
    const float* kbase = kv + (size_t)b * KK * (2 * DD) + (size_t)h * 64;
    for (int i = tid; i < KP * 16; i += 256) {
        int r = i >> 4, seg = i & 15;
        float4 kvv = z4, vvv = z4;
        if (r < KK) {
            kvv = *(const float4*)(kbase + (size_t)r * (2 * DD) + seg * 4);
            vvv = *(const float4*)(kbase + (size_t)r * (2 * DD) + DD + seg * 4);
        }
        unsigned* kd = Ks + r * KSTR + seg * 4;
        kd[0] = f2tf(kvv.x); kd[1] = f2tf(kvv.y); kd[2] = f2tf(kvv.z); kd[3] = f2tf(kvv.w);
        unsigned* vd = Vs + r * VSTR + seg * 4;
        vd[0] = f2tf(vvv.x); vd[1] = f2tf(vvv.y); vd[2] = f2tf(vvv.z); vd[3] = f2tf(vvv.w);
    }
    __syncthreads();

    // ---- QK^T : S[16 x 264] per warp ----
    const int wq = w * 16;
    unsigned aq[8][4];
#pragma unroll
    for (int kt = 0; kt < 8; kt++) {
        int kk = kt * 8;
        aq[kt][0] = Qs[(wq + g    ) * QSTR + kk + t4];
        aq[kt][1] = Qs[(wq + g + 8) * QSTR + kk + t4];
        aq[kt][2] = Qs[(wq + g    ) * QSTR + kk + t4 + 4];
        aq[kt][3] = Qs[(wq + g + 8) * QSTR + kk + t4 + 4];
    }

    float s[NJT][4];
#pragma unroll
    for (int j = 0; j < NJT; j++) {
        s[j][0] = s[j][1] = s[j][2] = s[j][3] = 0.f;
#pragma unroll
        for (int kt = 0; kt < 8; kt++) {
            unsigned bf[2];
            const unsigned* kp = Ks + (j * 8 + g) * KSTR + kt * 8 + t4;
            bf[0] = kp[0];
            bf[1] = kp[4];
            MMA_TF32(s[j], aq[kt], bf);
        }
    }

    // ---- scale + bias ----
    const int nrow0 = qb0 + wq + g;
    const int nrow1 = nrow0 + 8;
    const float* bp0 = bias + ((size_t)h * NN + (nrow0 < NN ? nrow0 : NN - 1)) * KK;
    const float* bp1 = bias + ((size_t)h * NN + (nrow1 < NN ? nrow1 : NN - 1)) * KK;
#pragma unroll
    for (int j = 0; j < NJT; j++) {
        int k0 = j * 8 + 2 * t4;
        s[j][0] = (k0     < KK) ? fmaf(s[j][0], 0.125f, bp0[k0])     : -1e30f;
        s[j][1] = (k0 + 1 < KK) ? fmaf(s[j][1], 0.125f, bp0[k0 + 1]) : -1e30f;
        s[j][2] = (k0     < KK) ? fmaf(s[j][2], 0.125f, bp1[k0])     : -1e30f;
        s[j][3] = (k0 + 1 < KK) ? fmaf(s[j][3], 0.125f, bp1[k0 + 1]) : -1e30f;
    }

    // ---- row softmax ----
    float m0 = -1e30f, m1 = -1e30f;
#pragma unroll
    for (int j = 0; j < NJT; j++) {
        m0 = fmaxf(m0, fmaxf(s[j][0], s[j][1]));
        m1 = fmaxf(m1, fmaxf(s[j][2], s[j][3]));
    }
    m0 = fmaxf(m0, __shfl_xor_sync(0xffffffffu, m0, 1));
    m0 = fmaxf(m0, __shfl_xor_sync(0xffffffffu, m0, 2));
    m1 = fmaxf(m1, __shfl_xor_sync(0xffffffffu, m1, 1));
    m1 = fmaxf(m1, __shfl_xor_sync(0xffffffffu, m1, 2));

    float l0 = 0.f, l1 = 0.f;
#pragma unroll
    for (int j = 0; j < NJT; j++) {
        s[j][0] = __expf(s[j][0] - m0); l0 += s[j][0];
        s[j][1] = __expf(s[j][1] - m0); l0 += s[j][1];
        s[j][2] = __expf(s[j][2] - m1); l1 += s[j][2];
        s[j][3] = __expf(s[j][3] - m1); l1 += s[j][3];
    }
    l0 += __shfl_xor_sync(0xffffffffu, l0, 1);
    l0 += __shfl_xor_sync(0xffffffffu, l0, 2);
    l1 += __shfl_xor_sync(0xffffffffu, l1, 1);
    l1 += __shfl_xor_sync(0xffffffffu, l1, 2);

    // ---- P @ V ----
    float ov[8][4];
#pragma unroll
    for (int t = 0; t < 8; t++)
        ov[t][0] = ov[t][1] = ov[t][2] = ov[t][3] = 0.f;

    const int src0 = (lane & ~3) | (t4 >> 1);
    const int src2 = src0 + 2;
    const bool odd = (t4 & 1);
#pragma unroll
    for (int j = 0; j < NJT; j++) {
        float v00 = __shfl_sync(0xffffffffu, s[j][0], src0);
        float v01 = __shfl_sync(0xffffffffu, s[j][1], src0);
        float v20 = __shfl_sync(0xffffffffu, s[j][2], src0);
        float v21 = __shfl_sync(0xffffffffu, s[j][3], src0);
        float w00 = __shfl_sync(0xffffffffu, s[j][0], src2);
        float w01 = __shfl_sync(0xffffffffu, s[j][1], src2);
        float w20 = __shfl_sync(0xffffffffu, s[j][2], src2);
        float w21 = __shfl_sync(0xffffffffu, s[j][3], src2);
        unsigned ap[4];
        ap[0] = f2tf(odd ? v01 : v00);
        ap[1] = f2tf(odd ? v21 : v20);
        ap[2] = f2tf(odd ? w01 : w00);
        ap[3] = f2tf(odd ? w21 : w20);
#pragma unroll
        for (int t = 0; t < 8; t++) {
            unsigned bf[2];
            const unsigned* vp = Vs + (j * 8 + t4) * VSTR + t * 8 + g;
            bf[0] = vp[0];
            bf[1] = vp[4 * VSTR];
            MMA_TF32(ov[t], ap, bf);
        }
    }

    // ---- epilogue ----
    const float inv0 = 1.f / l0, inv1 = 1.f / l1;
#pragma unroll
    for (int t = 0; t < 8; t++) {
        int col = h * 64 + t * 8 + 2 * t4;
        if (nrow0 < NN)
            *(float2*)(o + ((size_t)b * NN + nrow0) * DD + col) =
                make_float2(ov[t][0] * inv0, ov[t][1] * inv0);
        if (nrow1 < NN)
            *(float2*)(o + ((size_t)b * NN + nrow1) * DD + col) =
                make_float2(ov[t][2] * inv1, ov[t][3] * inv1);
    }
}

// ---------------- launch ----------------
extern "C" void kernel_launch(void* const* d_in, const int* in_sizes, int n_in,
                              void* d_out, int out_size)
{
    const float* x     = (const float*)d_in[0];
    const float* Wl    = (const float*)d_in[1];
    const float* Wq    = (const float*)d_in[2];
    const float* Wkv   = (const float*)d_in[3];
    const float* Wo    = (const float*)d_in[4];
    const float* bo    = (const float*)d_in[5];
    const float* w1    = (const float*)d_in[6];
    const float* b1    = (const float*)d_in[7];
    const float* w2    = (const float*)d_in[8];
    const float* b2    = (const float*)d_in[9];
    const float* feats = (const float*)d_in[10];
    const float* mask  = (const float*)d_in[11];
    float* out = (float*)d_out;

    float *ctx, *qb, *kvb, *biasb, *ob;
    cudaGetSymbolAddress((void**)&ctx,   g_ctx);
    cudaGetSymbolAddress((void**)&qb,    g_q);
    cudaGetSymbolAddress((void**)&kvb,   g_kv);
    cudaGetSymbolAddress((void**)&biasb, g_bias);
    cudaGetSymbolAddress((void**)&ob,    g_o);

    const int ATTN_SMEM = (QT * QSTR + KP * KSTR + KP * VSTR) * 4; // 182656 B
    cudaFuncSetAttribute(attn_mma, cudaFuncAttributeMaxDynamicSharedMemorySize,
                         ATTN_SMEM);
    cudaFuncSetAttribute(gemm_tf32, cudaFuncAttributeMaxDynamicSharedMemorySize,
                         GEMM_SMEM);

    // 1. pooled context (tile 0 = register-token copy)
    pool_kernel<<<dim3(KK, BB), 256>>>(x, Wl, ctx);
    // 2. Q = x @ Wq^T    [32800,768]
    gemm_tf32<<<dim3(6, 257), 256, GEMM_SMEM>>>(x, Wq, qb, BB * NN, DD, DD, nullptr);
    // 3. KV = ctx @ Wkv^T [8224,1536]
    gemm_tf32<<<dim3(12, 65), 256, GEMM_SMEM>>>(ctx, Wkv, kvb, BB * KK, 2 * DD, DD, nullptr);
    // 4. CPB bias [12,1025,257]
    cpb_kernel<<<(NK + 127) / 128, 128>>>(feats, mask, w1, b1, w2, b2, biasb);
    // 5. mma attention
    attn_mma<<<dim3((NN + QT - 1) / QT, HH, BB), 256, ATTN_SMEM>>>(qb, kvb, biasb, ob);
    // 6. out = o @ Wo^T + bo
    gemm_tf32<<<dim3(6, 257), 256, GEMM_SMEM>>>(ob, Wo, out, BB * NN, DD, DD, bo);
}

// round 14
// speedup vs baseline: 3.5639x; 1.0423x over previous
#include <cuda_runtime.h>
#include <math.h>

#define BB 32
#define NN 1025
#define DD 768
#define HH 12
#define KK 257   // context length
#define NK (NN*KK)

// ---------------- scratch (device globals; no allocs allowed) ----------------
__device__ float g_ctx [BB * KK * DD];        // [B,257,768]  (tf32-rounded)
__device__ float g_xr  [BB * NN * DD];        // tf32-rounded copy of x
__device__ float g_q   [BB * NN * DD];        // [B,1025,768]
__device__ float g_kv  [BB * KK * 2 * DD];    // [B,257,1536]  (k | v)
__device__ float g_bias[HH * NN * KK];        // [12,1025,257]
__device__ float g_o   [BB * NN * DD];        // [B,1025,768]  (tf32-rounded)
__device__ float g_wqr [DD * DD];             // tf32-rounded Wq
__device__ float g_wkvr[2 * DD * DD];         // tf32-rounded Wkv
__device__ float g_wor [DD * DD];             // tf32-rounded Wo

// ---------------- helpers ----------------
__device__ __forceinline__ unsigned f2tf(float f) {
    unsigned u; asm("cvt.rna.tf32.f32 %0, %1;" : "=r"(u) : "f"(f)); return u;
}
__device__ __forceinline__ float rtf(float f) {      // round fp32 -> tf32-in-fp32
    return __uint_as_float(f2tf(f));
}
__device__ __forceinline__ float4 rtf4(float4 v) {
    return make_float4(rtf(v.x), rtf(v.y), rtf(v.z), rtf(v.w));
}

#define MMA_TF32(cc, aa, bb)                                                   \
    asm volatile("mma.sync.aligned.m16n8k8.row.col.f32.tf32.tf32.f32 "         \
                 "{%0,%1,%2,%3}, {%4,%5,%6,%7}, {%8,%9}, {%0,%1,%2,%3};"       \
                 : "+f"(cc[0]), "+f"(cc[1]), "+f"(cc[2]), "+f"(cc[3])          \
                 : "r"(aa[0]), "r"(aa[1]), "r"(aa[2]), "r"(aa[3]),             \
                   "r"(bb[0]), "r"(bb[1]));

__device__ __forceinline__ void cp16(float* smem_dst, const float* gsrc, bool pred) {
    unsigned sa = (unsigned)__cvta_generic_to_shared(smem_dst);
    int sz = pred ? 16 : 0;
    asm volatile("cp.async.cg.shared.global [%0], [%1], 16, %2;"
                 :: "r"(sa), "l"(gsrc), "r"(sz));
}
#define CP_COMMIT() asm volatile("cp.async.commit_group;")
#define CP_WAIT2()  asm volatile("cp.async.wait_group 2;")

// ---------------- 0) tf32 rounding for weights ----------------
__global__ __launch_bounds__(256)
void round_kernel(const float* __restrict__ src, float* __restrict__ dst, int n4)
{
    int i = blockIdx.x * blockDim.x + threadIdx.x;
    if (i < n4) ((float4*)dst)[i] = rtf4(((const float4*)src)[i]);
}

// ---------------- 1) tiled local pooling -> ctx (+ rounded x copy) ---------
__global__ __launch_bounds__(256)
void pool_kernel(const float* __restrict__ x, const float* __restrict__ Wl,
                 float* __restrict__ ctx, float* __restrict__ xr)
{
    __shared__ float xs[4][768];
    __shared__ float red[4][8];
    __shared__ float ws[4];
    int t = blockIdx.x, b = blockIdx.y;
    int tid = threadIdx.x;
    const float* xb = x + (size_t)b * NN * DD;
    float* xrb = xr + (size_t)b * NN * DD;
    float* cout = ctx + ((size_t)b * KK + t) * DD;

    if (t == 0) {
        for (int i = tid; i < 192; i += 256) {
            float4 v = ((const float4*)xb)[i];
            float4 rv = rtf4(v);
            ((float4*)cout)[i] = rv;       // register token -> ctx (rounded)
            ((float4*)xrb)[i]  = rv;       // row 0 of rounded x
        }
        return;
    }
    int tt = t - 1, ti = tt >> 4, tj = tt & 15;
    int rows[4];
#pragma unroll
    for (int i = 0; i < 4; i++)
        rows[i] = 1 + (ti * 2 + (i >> 1)) * 32 + tj * 2 + (i & 1);

    for (int i = tid; i < 4 * 192; i += 256) {
        int rr = i / 192, seg = i - rr * 192;
        float4 v = ((const float4*)(xb + (size_t)rows[rr] * DD))[seg];
        ((float4*)&xs[rr][0])[seg] = v;
        // rounded stream-out of this x row (each row covered by exactly one block)
        ((float4*)(xrb + (size_t)rows[rr] * DD))[seg] = rtf4(v);
    }
    __syncthreads();

    float p0 = 0.f, p1 = 0.f, p2 = 0.f, p3 = 0.f;
    for (int dm = tid; dm < DD; dm += 256) {
        float wv = Wl[dm];
        p0 = fmaf(xs[0][dm], wv, p0);
        p1 = fmaf(xs[1][dm], wv, p1);
        p2 = fmaf(xs[2][dm], wv, p2);
        p3 = fmaf(xs[3][dm], wv, p3);
    }
#pragma unroll
    for (int off = 16; off; off >>= 1) {
        p0 += __shfl_xor_sync(0xffffffffu, p0, off);
        p1 += __shfl_xor_sync(0xffffffffu, p1, off);
        p2 += __shfl_xor_sync(0xffffffffu, p2, off);
        p3 += __shfl_xor_sync(0xffffffffu, p3, off);
    }
    if ((tid & 31) == 0) {
        int wgi = tid >> 5;
        red[0][wgi] = p0; red[1][wgi] = p1; red[2][wgi] = p2; red[3][wgi] = p3;
    }
    __syncthreads();
    if (tid == 0) {
        float s[4];
#pragma unroll
        for (int i = 0; i < 4; i++) {
            float a = 0.f;
#pragma unroll
            for (int wgi = 0; wgi < 8; wgi++) a += red[i][wgi];
            s[i] = a;
        }
        float mx = fmaxf(fmaxf(s[0], s[1]), fmaxf(s[2], s[3]));
        float e0 = __expf(s[0] - mx), e1 = __expf(s[1] - mx);
        float e2 = __expf(s[2] - mx), e3 = __expf(s[3] - mx);
        float inv = 1.f / (e0 + e1 + e2 + e3);
        ws[0] = e0 * inv; ws[1] = e1 * inv; ws[2] = e2 * inv; ws[3] = e3 * inv;
    }
    __syncthreads();
    for (int dm = tid; dm < DD; dm += 256) {
        cout[dm] = rtf(ws[0] * xs[0][dm] + ws[1] * xs[1][dm]
                     + ws[2] * xs[2][dm] + ws[3] * xs[3][dm]);
    }
}

// ---------------- 2) tf32 NT GEMM: 4-stage cp.async pipeline, occ=2 --------
// Operands are PRE-ROUNDED to tf32; raw bits feed mma directly (no in-loop cvt).
#define AS(s,r,k) gsm[(((s) * 128 + (r)) * 20) + (k)]
#define BS(s,r,k) gsm[10240 + (((s) * 128 + (r)) * 20) + (k)]

__global__ __launch_bounds__(256, 2)
void gemm_tf32(const float* __restrict__ A, const float* __restrict__ B,
               float* __restrict__ C, int M, int N, int K,
               const float* __restrict__ bias)
{
    extern __shared__ __align__(16) float gsm[];   // 2 * 10240 floats = 80KB

    const int tid  = threadIdx.x;
    const int lane = tid & 31, w = tid >> 5;
    const int g = lane >> 2, t4 = lane & 3;
    const int wm = (w >> 2) * 64;
    const int wn = (w & 3) * 32;
    const int bm = blockIdx.y * 128, bn = blockIdx.x * 128;

    const int lrow = tid >> 2;               // 0..63
    const int lk   = (tid & 3) << 2;         // 0,4,8,12

    const int ar0 = bm + lrow,      ar1 = bm + lrow + 64;
    const bool av0 = ar0 < M,       av1 = ar1 < M;
    const int ac0 = av0 ? ar0 : 0,  ac1 = av1 ? ar1 : 0;
    const int br0 = bn + lrow,      br1 = bn + lrow + 64;   // always valid

    float c[4][4][4];
#pragma unroll
    for (int i = 0; i < 4; i++)
#pragma unroll
        for (int j = 0; j < 4; j++)
#pragma unroll
            for (int e = 0; e < 4; e++) c[i][j][e] = 0.f;

    const int nkt = K / 16;

    // ---- prologue: fill stages 0..2 ----
#pragma unroll
    for (int s = 0; s < 3; s++) {
        const int k0 = s * 16;
        cp16(&AS(s, lrow,      lk), A + (size_t)ac0 * K + k0 + lk, av0);
        cp16(&AS(s, lrow + 64, lk), A + (size_t)ac1 * K + k0 + lk, av1);
        cp16(&BS(s, lrow,      lk), B + (size_t)br0 * K + k0 + lk, true);
        cp16(&BS(s, lrow + 64, lk), B + (size_t)br1 * K + k0 + lk, true);
        CP_COMMIT();
    }

    for (int kt = 0; kt < nkt; kt++) {
        CP_WAIT2();
        __syncthreads();
        const int st = kt & 3;

#pragma unroll
        for (int ks = 0; ks < 2; ks++) {
            const int kk = ks * 8;
            unsigned af[4][4], bf[4][2];
#pragma unroll
            for (int i = 0; i < 4; i++) {
                int r = wm + i * 16 + g;
                af[i][0] = __float_as_uint(AS(st, r,     kk + t4));
                af[i][1] = __float_as_uint(AS(st, r + 8, kk + t4));
                af[i][2] = __float_as_uint(AS(st, r,     kk + t4 + 4));
                af[i][3] = __float_as_uint(AS(st, r + 8, kk + t4 + 4));
            }
#pragma unroll
            for (int j = 0; j < 4; j++) {
                int r = wn + j * 8 + g;
                bf[j][0] = __float_as_uint(BS(st, r, kk + t4));
                bf[j][1] = __float_as_uint(BS(st, r, kk + t4 + 4));
            }
#pragma unroll
            for (int i = 0; i < 4; i++)
#pragma unroll
                for (int j = 0; j < 4; j++)
                    MMA_TF32(c[i][j], af[i], bf[j]);
        }

        const int pf = kt + 3;
        if (pf < nkt) {
            const int s = pf & 3, k0 = pf * 16;
            cp16(&AS(s, lrow,      lk), A + (size_t)ac0 * K + k0 + lk, av0);
            cp16(&AS(s, lrow + 64, lk), A + (size_t)ac1 * K + k0 + lk, av1);
            cp16(&BS(s, lrow,      lk), B + (size_t)br0 * K + k0 + lk, true);
            cp16(&BS(s, lrow + 64, lk), B + (size_t)br1 * K + k0 + lk, true);
        }
        CP_COMMIT();
    }

    // ---- epilogue ----
#pragma unroll
    for (int j = 0; j < 4; j++) {
        const int col = bn + wn + j * 8 + t4 * 2;
        float b0 = bias ? bias[col] : 0.f;
        float b1 = bias ? bias[col + 1] : 0.f;
#pragma unroll
        for (int i = 0; i < 4; i++) {
            int r0 = bm + wm + i * 16 + g;
            if (r0 < M)
                *(float2*)(C + (size_t)r0 * N + col) =
                    make_float2(c[i][j][0] + b0, c[i][j][1] + b1);
            int r1 = r0 + 8;
            if (r1 < M)
                *(float2*)(C + (size_t)r1 * N + col) =
                    make_float2(c[i][j][2] + b0, c[i][j][3] + b1);
        }
    }
}
#define GEMM_SMEM (2 * 4 * 128 * 20 * 4)   // 81920 bytes

// ---------------- 3) CPB relative-position bias ----------------
__global__ __launch_bounds__(128)
void cpb_kernel(const float* __restrict__ feats, const float* __restrict__ mask,
                const float* __restrict__ w1, const float* __restrict__ b1,
                const float* __restrict__ w2, const float* __restrict__ b2,
                float* __restrict__ bias)
{
    int idx = blockIdx.x * blockDim.x + threadIdx.x;
    if (idx >= NK) return;
    float f0 = feats[2 * idx], f1 = feats[2 * idx + 1];
    float m = mask[idx];
    float h[32];
#pragma unroll
    for (int c = 0; c < 32; c++) {
        float t = fmaf(f0, w1[2 * c], fmaf(f1, w1[2 * c + 1], b1[c]));
        h[c] = 0.5f * t * (1.f + erff(t * 0.7071067811865475f));
    }
#pragma unroll
    for (int hh = 0; hh < HH; hh++) {
        float s = b2[hh];
#pragma unroll
        for (int c = 0; c < 32; c++) s = fmaf(w2[hh * 32 + c], h[c], s);
        bias[(size_t)hh * NK + idx] = s * m;
    }
}

// ---------------- 4) mma flash attention (writes tf32-rounded o) -----------
#define QT   128
#define KP   264
#define NJT  33     // KP/8
#define QSTR 68
#define KSTR 68
#define VSTR 72

__global__ __launch_bounds__(256, 1)
void attn_mma(const float* __restrict__ q, const float* __restrict__ kv,
              const float* __restrict__ bias, float* __restrict__ o)
{
    extern __shared__ unsigned smu[];
    unsigned* Qs = smu;                       // [128][68]
    unsigned* Ks = Qs + QT * QSTR;            // [264][68]
    unsigned* Vs = Ks + KP * KSTR;            // [264][72]

    const int qb0 = blockIdx.x * QT;
    const int h = blockIdx.y, b = blockIdx.z;
    const int tid = threadIdx.x, w = tid >> 5, lane = tid & 31;
    const int g = lane >> 2, t4 = lane & 3;
    const float4 z4 = make_float4(0.f, 0.f, 0.f, 0.f);

    // ---- stage Q (tf32) ----
    const float* qbase = q + (size_t)b * NN * DD + (size_t)h * 64;
    for (int i = tid; i < QT * 16; i += 256) {
        int r = i >> 4, seg = i & 15;
        int n = qb0 + r;
        float4 v = (n < NN) ? *(const float4*)(qbase + (size_t)n * DD + seg * 4) : z4;
        unsigned* dst = Qs + r * QSTR + seg * 4;
        dst[0] = f2tf(v.x); dst[1] = f2tf(v.y); dst[2] = f2tf(v.z); dst[3] = f2tf(v.w);
    }
    // ---- stage K, V (tf32) ----
    const float* kbase = kv + (size_t)b * KK * (2 * DD) + (size_t)h * 64;
    for (int i = tid; i < KP * 16; i += 256) {
        int r = i >> 4, seg = i & 15;
        float4 kvv = z4, vvv = z4;
        if (r < KK) {
            kvv = *(const float4*)(kbase + (size_t)r * (2 * DD) + seg * 4);
            vvv = *(const float4*)(kbase + (size_t)r * (2 * DD) + DD + seg * 4);
        }
        unsigned* kd = Ks + r * KSTR + seg * 4;
        kd[0] = f2tf(kvv.x); kd[1] = f2tf(kvv.y); kd[2] = f2tf(kvv.z); kd[3] = f2tf(kvv.w);
        unsigned* vd = Vs + r * VSTR + seg * 4;
        vd[0] = f2tf(vvv.x); vd[1] = f2tf(vvv.y); vd[2] = f2tf(vvv.z); vd[3] = f2tf(vvv.w);
    }
    __syncthreads();

    // ---- QK^T : S[16 x 264] per warp ----
    const int wq = w * 16;
    unsigned aq[8][4];
#pragma unroll
    for (int kt = 0; kt < 8; kt++) {
        int kk = kt * 8;
        aq[kt][0] = Qs[(wq + g    ) * QSTR + kk + t4];
        aq[kt][1] = Qs[(wq + g + 8) * QSTR + kk + t4];
        aq[kt][2] = Qs[(wq + g    ) * QSTR + kk + t4 + 4];
        aq[kt][3] = Qs[(wq + g + 8) * QSTR + kk + t4 + 4];
    }

    float s[NJT][4];
#pragma unroll
    for (int j = 0; j < NJT; j++) {
        s[j][0] = s[j][1] = s[j][2] = s[j][3] = 0.f;
#pragma unroll
        for (int kt = 0; kt < 8; kt++) {
            unsigned bf[2];
            const unsigned* kp = Ks + (j * 8 + g) * KSTR + kt * 8 + t4;
            bf[0] = kp[0];
            bf[1] = kp[4];
            MMA_TF32(s[j], aq[kt], bf);
        }
    }

    // ---- scale + bias ----
    const int nrow0 = qb0 + wq + g;
    const int nrow1 = nrow0 + 8;
    const float* bp0 = bias + ((size_t)h * NN + (nrow0 < NN ? nrow0 : NN - 1)) * KK;
    const float* bp1 = bias + ((size_t)h * NN + (nrow1 < NN ? nrow1 : NN - 1)) * KK;
#pragma unroll
    for (int j = 0; j < NJT; j++) {
        int k0 = j * 8 + 2 * t4;
        s[j][0] = (k0     < KK) ? fmaf(s[j][0], 0.125f, bp0[k0])     : -1e30f;
        s[j][1] = (k0 + 1 < KK) ? fmaf(s[j][1], 0.125f, bp0[k0 + 1]) : -1e30f;
        s[j][2] = (k0     < KK) ? fmaf(s[j][2], 0.125f, bp1[k0])     : -1e30f;
        s[j][3] = (k0 + 1 < KK) ? fmaf(s[j][3], 0.125f, bp1[k0 + 1]) : -1e30f;
    }

    // ---- row softmax ----
    float m0 = -1e30f, m1 = -1e30f;
#pragma unroll
    for (int j = 0; j < NJT; j++) {
        m0 = fmaxf(m0, fmaxf(s[j][0], s[j][1]));
        m1 = fmaxf(m1, fmaxf(s[j][2], s[j][3]));
    }
    m0 = fmaxf(m0, __shfl_xor_sync(0xffffffffu, m0, 1));
    m0 = fmaxf(m0, __shfl_xor_sync(0xffffffffu, m0, 2));
    m1 = fmaxf(m1, __shfl_xor_sync(0xffffffffu, m1, 1));
    m1 = fmaxf(m1, __shfl_xor_sync(0xffffffffu, m1, 2));

    float l0 = 0.f, l1 = 0.f;
#pragma unroll
    for (int j = 0; j < NJT; j++) {
        s[j][0] = __expf(s[j][0] - m0); l0 += s[j][0];
        s[j][1] = __expf(s[j][1] - m0); l0 += s[j][1];
        s[j][2] = __expf(s[j][2] - m1); l1 += s[j][2];
        s[j][3] = __expf(s[j][3] - m1); l1 += s[j][3];
    }
    l0 += __shfl_xor_sync(0xffffffffu, l0, 1);
    l0 += __shfl_xor_sync(0xffffffffu, l0, 2);
    l1 += __shfl_xor_sync(0xffffffffu, l1, 1);
    l1 += __shfl_xor_sync(0xffffffffu, l1, 2);

    // ---- P @ V ----
    float ov[8][4];
#pragma unroll
    for (int t = 0; t < 8; t++)
        ov[t][0] = ov[t][1] = ov[t][2] = ov[t][3] = 0.f;

    const int src0 = (lane & ~3) | (t4 >> 1);
    const int src2 = src0 + 2;
    const bool odd = (t4 & 1);
#pragma unroll
    for (int j = 0; j < NJT; j++) {
        float v00 = __shfl_sync(0xffffffffu, s[j][0], src0);
        float v01 = __shfl_sync(0xffffffffu, s[j][1], src0);
        float v20 = __shfl_sync(0xffffffffu, s[j][2], src0);
        float v21 = __shfl_sync(0xffffffffu, s[j][3], src0);
        float w00 = __shfl_sync(0xffffffffu, s[j][0], src2);
        float w01 = __shfl_sync(0xffffffffu, s[j][1], src2);
        float w20 = __shfl_sync(0xffffffffu, s[j][2], src2);
        float w21 = __shfl_sync(0xffffffffu, s[j][3], src2);
        unsigned ap[4];
        ap[0] = f2tf(odd ? v01 : v00);
        ap[1] = f2tf(odd ? v21 : v20);
        ap[2] = f2tf(odd ? w01 : w00);
        ap[3] = f2tf(odd ? w21 : w20);
#pragma unroll
        for (int t = 0; t < 8; t++) {
            unsigned bf[2];
            const unsigned* vp = Vs + (j * 8 + t4) * VSTR + t * 8 + g;
            bf[0] = vp[0];
            bf[1] = vp[4 * VSTR];
            MMA_TF32(ov[t], ap, bf);
        }
    }

    // ---- epilogue: normalize, round to tf32, store ----
    const float inv0 = 1.f / l0, inv1 = 1.f / l1;
#pragma unroll
    for (int t = 0; t < 8; t++) {
        int col = h * 64 + t * 8 + 2 * t4;
        if (nrow0 < NN)
            *(float2*)(o + ((size_t)b * NN + nrow0) * DD + col) =
                make_float2(rtf(ov[t][0] * inv0), rtf(ov[t][1] * inv0));
        if (nrow1 < NN)
            *(float2*)(o + ((size_t)b * NN + nrow1) * DD + col) =
                make_float2(rtf(ov[t][2] * inv1), rtf(ov[t][3] * inv1));
    }
}

// ---------------- launch ----------------
extern "C" void kernel_launch(void* const* d_in, const int* in_sizes, int n_in,
                              void* d_out, int out_size)
{
    const float* x     = (const float*)d_in[0];
    const float* Wl    = (const float*)d_in[1];
    const float* Wq    = (const float*)d_in[2];
    const float* Wkv   = (const float*)d_in[3];
    const float* Wo    = (const float*)d_in[4];
    const float* bo    = (const float*)d_in[5];
    const float* w1    = (const float*)d_in[6];
    const float* b1    = (const float*)d_in[7];
    const float* w2    = (const float*)d_in[8];
    const float* b2    = (const float*)d_in[9];
    const float* feats = (const float*)d_in[10];
    const float* mask  = (const float*)d_in[11];
    float* out = (float*)d_out;

    float *ctx, *xr, *qb, *kvb, *biasb, *ob, *wqr, *wkvr, *wor;
    cudaGetSymbolAddress((void**)&ctx,   g_ctx);
    cudaGetSymbolAddress((void**)&xr,    g_xr);
    cudaGetSymbolAddress((void**)&qb,    g_q);
    cudaGetSymbolAddress((void**)&kvb,   g_kv);
    cudaGetSymbolAddress((void**)&biasb, g_bias);
    cudaGetSymbolAddress((void**)&ob,    g_o);
    cudaGetSymbolAddress((void**)&wqr,   g_wqr);
    cudaGetSymbolAddress((void**)&wkvr,  g_wkvr);
    cudaGetSymbolAddress((void**)&wor,   g_wor);

    const int ATTN_SMEM = (QT * QSTR + KP * KSTR + KP * VSTR) * 4; // 182656 B
    cudaFuncSetAttribute(attn_mma, cudaFuncAttributeMaxDynamicSharedMemorySize,
                         ATTN_SMEM);
    cudaFuncSetAttribute(gemm_tf32, cudaFuncAttributeMaxDynamicSharedMemorySize,
                         GEMM_SMEM);

    // 0. round weights to tf32 (tiny)
    const int W1N4 = DD * DD / 4, W2N4 = 2 * DD * DD / 4;
    round_kernel<<<(W1N4 + 255) / 256, 256>>>(Wq,  wqr,  W1N4);
    round_kernel<<<(W2N4 + 255) / 256, 256>>>(Wkv, wkvr, W2N4);
    round_kernel<<<(W1N4 + 255) / 256, 256>>>(Wo,  wor,  W1N4);
    // 1. pooled context (rounded) + rounded x copy
    pool_kernel<<<dim3(KK, BB), 256>>>(x, Wl, ctx, xr);
    // 2. Q = xr @ Wq^T    [32800,768]
    gemm_tf32<<<dim3(6, 257), 256, GEMM_SMEM>>>(xr, wqr, qb, BB * NN, DD, DD, nullptr);
    // 3. KV = ctx @ Wkv^T [8224,1536]
    gemm_tf32<<<dim3(12, 65), 256, GEMM_SMEM>>>(ctx, wkvr, kvb, BB * KK, 2 * DD, DD, nullptr);
    // 4. CPB bias [12,1025,257]
    cpb_kernel<<<(NK + 127) / 128, 128>>>(feats, mask, w1, b1, w2, b2, biasb);
    // 5. mma attention (writes rounded o)
    attn_mma<<<dim3((NN + QT - 1) / QT, HH, BB), 256, ATTN_SMEM>>>(qb, kvb, biasb, ob);
    // 6. out = o @ Wo^T + bo
    gemm_tf32<<<dim3(6, 257), 256, GEMM_SMEM>>>(ob, wor, out, BB * NN, DD, DD, bo);
}